// round 1
// baseline (speedup 1.0000x reference)
#include <cuda_runtime.h>
#include <math.h>

// Problem constants
#define QC 16777216          // 2^24 = Bw*N*(C/3) — the tile() wrap period
#define MASKQ 0xFFFFFF
#define NROWS 65536          // Bw*N = 1024*64
#define CDIM 768

// Scratch (device globals: allocation-free per harness rules)
__device__ float g_F[3 * QC];   // LN1 output in window order; later reused for attention output
__device__ float g_q[3 * QC];   // q (win, head, n, d); later reused for proj output
__device__ float g_k[3 * QC];   // k (win, head, n, d)
__device__ float g_v[3 * QC];   // v (win, head, n, d)

// ---------------------------------------------------------------------------
// Block-wide reduction of two floats (256 threads = 8 warps)
// ---------------------------------------------------------------------------
__device__ __forceinline__ void blockReduce2(float& a, float& b, float* sh) {
#pragma unroll
    for (int o = 16; o; o >>= 1) {
        a += __shfl_xor_sync(0xffffffffu, a, o);
        b += __shfl_xor_sync(0xffffffffu, b, o);
    }
    int w = threadIdx.x >> 5;
    if ((threadIdx.x & 31) == 0) { sh[w] = a; sh[w + 8] = b; }
    __syncthreads();
    if (threadIdx.x == 0) {
        float sa = 0.f, sb = 0.f;
#pragma unroll
        for (int i = 0; i < 8; i++) { sa += sh[i]; sb += sh[i + 8]; }
        sh[16] = sa; sh[17] = sb;
    }
    __syncthreads();
    a = sh[16]; b = sh[17];
    __syncthreads();   // safe smem reuse by a subsequent reduction
}

// ---------------------------------------------------------------------------
// K1: LayerNorm1 + window partition.  One block per row (768 elems).
//   src row r of x  ->  g_F row (win*64 + n)
// ---------------------------------------------------------------------------
__global__ __launch_bounds__(256) void k_ln1(const float* __restrict__ x,
                                             const float* __restrict__ g,
                                             const float* __restrict__ b) {
    __shared__ float sh[32];
    int r  = blockIdx.x;
    int bb = r >> 14;            // batch
    int l  = r & 16383;
    int hh = l >> 7, ww = l & 127;
    int win = (bb * 16 + (hh >> 3)) * 16 + (ww >> 3);
    int n   = (hh & 7) * 8 + (ww & 7);

    const float* xr = x + (size_t)r * CDIM;
    int c0 = threadIdx.x, c1 = threadIdx.x + 256, c2 = threadIdx.x + 512;
    float v0 = xr[c0], v1 = xr[c1], v2 = xr[c2];
    float s  = v0 + v1 + v2;
    float sq = v0 * v0 + v1 * v1 + v2 * v2;
    blockReduce2(s, sq, sh);
    float mean = s * (1.f / 768.f);
    float var  = sq * (1.f / 768.f) - mean * mean;
    float rs   = rsqrtf(var + 1e-5f);

    float* dst = g_F + (size_t)(win * 64 + n) * CDIM;
    dst[c0] = (v0 - mean) * rs * g[c0] + b[c0];
    dst[c1] = (v1 - mean) * rs * g[c1] + b[c1];
    dst[c2] = (v2 - mean) * rs * g[c2] + b[c2];
}

// ---------------------------------------------------------------------------
// K2: QKV GEMM.  out[r][j] = sum_c A(r,c) * qkv_w[j][c]
//   j in [0,768):    A = green+blue = F[QC + m] + F[2QC + m], m = (r*768+c)&MASKQ  -> g_q
//   j in [768,1536): A = red = F[m]                                               -> g_k
//   j in [1536,2304):A = red                                                      -> g_v
// Tiles: BM=BN=128, BK=8, 256 threads, 8x8 per-thread microtile.
// ---------------------------------------------------------------------------
__global__ __launch_bounds__(256) void k_gemm_qkv(const float* __restrict__ W) {
    __shared__ float As[8][128];
    __shared__ float Bs[8][128];
    const int m0 = blockIdx.x * 128;
    const int n0 = blockIdx.y * 128;
    const int sec = (n0 >= 1536) ? 2 : (n0 >= 768 ? 1 : 0);
    const bool isQ = (sec == 0);

    const int tx = threadIdx.x & 15, ty = threadIdx.x >> 4;
    const int lrow = threadIdx.x >> 1, lcol = (threadIdx.x & 1) * 4;

    float acc[8][8];
#pragma unroll
    for (int i = 0; i < 8; i++)
#pragma unroll
        for (int j = 0; j < 8; j++) acc[i][j] = 0.f;

    for (int k0 = 0; k0 < CDIM; k0 += 8) {
        // A tile (gathered)
        int base = (m0 + lrow) * CDIM + k0 + lcol;
#pragma unroll
        for (int u = 0; u < 4; u++) {
            int idx = (base + u) & MASKQ;
            float v = isQ ? (g_F[QC + idx] + g_F[2 * QC + idx]) : g_F[idx];
            As[lcol + u][lrow] = v;
        }
        // B tile: W[(n0+lrow)][k0+lcol..+3]
        float4 bv = *(const float4*)&W[(n0 + lrow) * CDIM + k0 + lcol];
        Bs[lcol + 0][lrow] = bv.x;
        Bs[lcol + 1][lrow] = bv.y;
        Bs[lcol + 2][lrow] = bv.z;
        Bs[lcol + 3][lrow] = bv.w;
        __syncthreads();

#pragma unroll
        for (int kk = 0; kk < 8; kk++) {
            float a[8], bb[8];
            *(float4*)&a[0]  = *(const float4*)&As[kk][ty * 8];
            *(float4*)&a[4]  = *(const float4*)&As[kk][ty * 8 + 4];
            *(float4*)&bb[0] = *(const float4*)&Bs[kk][tx * 8];
            *(float4*)&bb[4] = *(const float4*)&Bs[kk][tx * 8 + 4];
#pragma unroll
            for (int i = 0; i < 8; i++)
#pragma unroll
                for (int j = 0; j < 8; j++) acc[i][j] += a[i] * bb[j];
        }
        __syncthreads();
    }

    float* outp = (sec == 0) ? g_q : (sec == 1 ? g_k : g_v);
    const int nbase = n0 - sec * CDIM;
#pragma unroll
    for (int i = 0; i < 8; i++) {
        int row = m0 + ty * 8 + i;
        int win = row >> 6, nn = row & 63;
#pragma unroll
        for (int j = 0; j < 8; j++) {
            int col  = nbase + tx * 8 + j;
            int head = col >> 6, d = col & 63;
            outp[win * 49152 + head * 4096 + nn * 64 + d] = acc[i][j];
        }
    }
}

// ---------------------------------------------------------------------------
// K3: windowed attention, one block per (window, head).  N=64, D=64.
//   S = q k^T * 0.125; softmax rows; O = P v.  Writes to g_F in (row, head*64+d).
// ---------------------------------------------------------------------------
__global__ __launch_bounds__(256) void k_attn() {
    __shared__ float sA[64 * 68];   // q, then reused for P
    __shared__ float sB[64 * 68];   // k, then reused for v
    const int wh = blockIdx.x;      // win*12 + head
    const float* qp = g_q + (size_t)wh * 4096;
    const float* kp = g_k + (size_t)wh * 4096;
    const float* vp = g_v + (size_t)wh * 4096;
    const int tid = threadIdx.x;

#pragma unroll
    for (int u = 0; u < 16; u++) {
        int idx = tid + u * 256;
        int so  = (idx >> 6) * 68 + (idx & 63);
        sA[so] = qp[idx];
        sB[so] = kp[idx];
    }
    __syncthreads();

    const int i  = tid >> 2;    // row 0..63
    const int jl = tid & 3;     // col-lane
    float acc[16];
#pragma unroll
    for (int jj = 0; jj < 16; jj++) acc[jj] = 0.f;

    for (int c = 0; c < 64; c++) {
        float qv = sA[i * 68 + c];
#pragma unroll
        for (int jj = 0; jj < 16; jj++)
            acc[jj] += qv * sB[(jl + 4 * jj) * 68 + c];
    }

    // softmax over the row (16 regs x 4 lanes)
    float mx = -1e30f;
#pragma unroll
    for (int jj = 0; jj < 16; jj++) { acc[jj] *= 0.125f; mx = fmaxf(mx, acc[jj]); }
    mx = fmaxf(mx, __shfl_xor_sync(0xffffffffu, mx, 1));
    mx = fmaxf(mx, __shfl_xor_sync(0xffffffffu, mx, 2));
    float sum = 0.f;
#pragma unroll
    for (int jj = 0; jj < 16; jj++) { acc[jj] = __expf(acc[jj] - mx); sum += acc[jj]; }
    sum += __shfl_xor_sync(0xffffffffu, sum, 1);
    sum += __shfl_xor_sync(0xffffffffu, sum, 2);
    float inv = 1.f / sum;

    __syncthreads();   // everyone done reading q/k
#pragma unroll
    for (int jj = 0; jj < 16; jj++) sA[i * 68 + jl + 4 * jj] = acc[jj] * inv;
#pragma unroll
    for (int u = 0; u < 16; u++) {
        int idx = tid + u * 256;
        sB[(idx >> 6) * 68 + (idx & 63)] = vp[idx];
    }
    __syncthreads();

    float o[16];
#pragma unroll
    for (int dd = 0; dd < 16; dd++) o[dd] = 0.f;
    for (int j = 0; j < 64; j++) {
        float pv = sA[i * 68 + j];
#pragma unroll
        for (int dd = 0; dd < 16; dd++)
            o[dd] += pv * sB[j * 68 + jl + 4 * dd];
    }

    const int win = wh / 12, head = wh % 12;
    float* dst = g_F + (size_t)(win * 64 + i) * CDIM + head * 64;
#pragma unroll
    for (int dd = 0; dd < 16; dd++) dst[jl + 4 * dd] = o[dd];
}

// ---------------------------------------------------------------------------
// K4: projection GEMM. out[r][j] = sum_c g_F[r][c] * proj_w[j][c] + proj_b[j]
// Writes into g_q (row-linear).
// ---------------------------------------------------------------------------
__global__ __launch_bounds__(256) void k_gemm_proj(const float* __restrict__ W,
                                                   const float* __restrict__ bias) {
    __shared__ float As[8][128];
    __shared__ float Bs[8][128];
    const int m0 = blockIdx.x * 128;
    const int n0 = blockIdx.y * 128;
    const int tx = threadIdx.x & 15, ty = threadIdx.x >> 4;
    const int lrow = threadIdx.x >> 1, lcol = (threadIdx.x & 1) * 4;

    float acc[8][8];
#pragma unroll
    for (int i = 0; i < 8; i++)
#pragma unroll
        for (int j = 0; j < 8; j++) acc[i][j] = 0.f;

    for (int k0 = 0; k0 < CDIM; k0 += 8) {
        float4 av = *(const float4*)&g_F[(m0 + lrow) * CDIM + k0 + lcol];
        As[lcol + 0][lrow] = av.x;
        As[lcol + 1][lrow] = av.y;
        As[lcol + 2][lrow] = av.z;
        As[lcol + 3][lrow] = av.w;
        float4 bv = *(const float4*)&W[(n0 + lrow) * CDIM + k0 + lcol];
        Bs[lcol + 0][lrow] = bv.x;
        Bs[lcol + 1][lrow] = bv.y;
        Bs[lcol + 2][lrow] = bv.z;
        Bs[lcol + 3][lrow] = bv.w;
        __syncthreads();

#pragma unroll
        for (int kk = 0; kk < 8; kk++) {
            float a[8], bb[8];
            *(float4*)&a[0]  = *(const float4*)&As[kk][ty * 8];
            *(float4*)&a[4]  = *(const float4*)&As[kk][ty * 8 + 4];
            *(float4*)&bb[0] = *(const float4*)&Bs[kk][tx * 8];
            *(float4*)&bb[4] = *(const float4*)&Bs[kk][tx * 8 + 4];
#pragma unroll
            for (int i = 0; i < 8; i++)
#pragma unroll
                for (int j = 0; j < 8; j++) acc[i][j] += a[i] * bb[j];
        }
        __syncthreads();
    }

#pragma unroll
    for (int i = 0; i < 8; i++) {
        int row = m0 + ty * 8 + i;
#pragma unroll
        for (int j = 0; j < 8; j++) {
            int col = n0 + tx * 8 + j;
            g_q[row * CDIM + col] = acc[i][j] + bias[col];
        }
    }
}

// ---------------------------------------------------------------------------
// K5: LN2 + fc1 (row dot) + exact GELU + fc2 (outer product) + biases.
// One block per row.  Output order is already the final order (reference does
// NOT undo the window permutation).
// ---------------------------------------------------------------------------
__global__ __launch_bounds__(256) void k_final(const float* __restrict__ g2,
                                               const float* __restrict__ b2,
                                               const float* __restrict__ fc1w,
                                               const float* __restrict__ fc1b,
                                               const float* __restrict__ fc2w,
                                               const float* __restrict__ fc2b,
                                               float* __restrict__ out) {
    __shared__ float sh[32];
    int r = blockIdx.x;
    const float* pr = g_q + (size_t)r * CDIM;
    int c0 = threadIdx.x, c1 = threadIdx.x + 256, c2 = threadIdx.x + 512;
    float v0 = pr[c0], v1 = pr[c1], v2 = pr[c2];

    float s  = v0 + v1 + v2;
    float sq = v0 * v0 + v1 * v1 + v2 * v2;
    blockReduce2(s, sq, sh);
    float mean = s * (1.f / 768.f);
    float var  = sq * (1.f / 768.f) - mean * mean;
    float rs   = rsqrtf(var + 1e-5f);

    float a0 = (v0 - mean) * rs * g2[c0] + b2[c0];
    float a1 = (v1 - mean) * rs * g2[c1] + b2[c1];
    float a2 = (v2 - mean) * rs * g2[c2] + b2[c2];

    float dotp = a0 * fc1w[c0] + a1 * fc1w[c1] + a2 * fc1w[c2];
    float zero = 0.f;
    blockReduce2(dotp, zero, sh);
    float t  = dotp + fc1b[0];
    float hd = 0.5f * t * (1.f + erff(t * 0.70710678118654752f));   // exact GELU

    float* orow = out + (size_t)r * CDIM;
    orow[c0] = hd * fc2w[c0] + fc2b[c0];
    orow[c1] = hd * fc2w[c1] + fc2b[c1];
    orow[c2] = hd * fc2w[c2] + fc2b[c2];
}

// ---------------------------------------------------------------------------
extern "C" void kernel_launch(void* const* d_in, const int* in_sizes, int n_in,
                              void* d_out, int out_size) {
    const float* x     = (const float*)d_in[0];
    const float* n1g   = (const float*)d_in[1];
    const float* n1b   = (const float*)d_in[2];
    const float* n2g   = (const float*)d_in[3];
    const float* n2b   = (const float*)d_in[4];
    const float* qkvw  = (const float*)d_in[5];
    const float* projw = (const float*)d_in[6];
    const float* projb = (const float*)d_in[7];
    const float* fc1w  = (const float*)d_in[8];
    const float* fc1b  = (const float*)d_in[9];
    const float* fc2w  = (const float*)d_in[10];
    const float* fc2b  = (const float*)d_in[11];

    k_ln1<<<NROWS, 256>>>(x, n1g, n1b);

    dim3 gq(NROWS / 128, 2304 / 128);       // (512, 18)
    k_gemm_qkv<<<gq, 256>>>(qkvw);

    k_attn<<<1024 * 12, 256>>>();

    dim3 gp(NROWS / 128, CDIM / 128);       // (512, 6)
    k_gemm_proj<<<gp, 256>>>(projw, projb);

    k_final<<<NROWS, 256>>>(n2g, n2b, fc1w, fc1b, fc2w, fc2b, (float*)d_out);
}

// round 3
// speedup vs baseline: 2.6592x; 2.6592x over previous
#include <cuda_runtime.h>
#include <math.h>
#include <stdint.h>

// ---------------------------------------------------------------------------
// Problem constants
// ---------------------------------------------------------------------------
#define QC 16777216          // 2^24 = Bw*N*(C/3) — the tile() wrap period
#define MASKQ 0xFFFFFF
#define NROWS 65536          // 1024 windows * 64 tokens
#define CDIM 768

// Scratch (device globals: allocation-free per harness rules)
__device__ __align__(16) float g_Ared[3 * QC];  // red A (65536x768); later reused as attention output
__device__ __align__(16) float g_Aq[3 * QC];    // green+blue A; later reused as proj output
__device__ __align__(16) float g_gb[2 * QC];    // staging: green third, blue third
__device__ __align__(16) float g_q[3 * QC];     // q (win, head, n, d)
__device__ __align__(16) float g_k[3 * QC];     // k
__device__ __align__(16) float g_v[3 * QC];     // v
__device__ __align__(16) float g_Wqkv[2304 * 768];  // tf32-rounded weights
__device__ __align__(16) float g_Wproj[768 * 768];

// ---------------------------------------------------------------------------
// Helpers
// ---------------------------------------------------------------------------
__device__ __forceinline__ float tf32r(float x) {
    uint32_t r;
    asm("cvt.rna.tf32.f32 %0, %1;" : "=r"(r) : "f"(x));
    return __uint_as_float(r);
}

__device__ __forceinline__ uint32_t smem_u32(const void* p) {
    uint32_t a;
    asm("{ .reg .u64 t; cvta.to.shared.u64 t, %1; cvt.u32.u64 %0, t; }" : "=r"(a) : "l"(p));
    return a;
}

__device__ __forceinline__ void cp16(uint32_t dst, const void* src) {
    asm volatile("cp.async.cg.shared.global [%0], [%1], 16;" :: "r"(dst), "l"(src));
}
#define CP_COMMIT() asm volatile("cp.async.commit_group;")
#define CP_WAIT1()  asm volatile("cp.async.wait_group 1;")

__device__ __forceinline__ void mma_tf32(float* c, const uint32_t* a, const uint32_t* b) {
    asm volatile(
        "mma.sync.aligned.m16n8k8.row.col.f32.tf32.tf32.f32 "
        "{%0,%1,%2,%3}, {%4,%5,%6,%7}, {%8,%9}, {%0,%1,%2,%3};"
        : "+f"(c[0]), "+f"(c[1]), "+f"(c[2]), "+f"(c[3])
        : "r"(a[0]), "r"(a[1]), "r"(a[2]), "r"(a[3]), "r"(b[0]), "r"(b[1]));
}

// ---------------------------------------------------------------------------
// Block-wide reduction of two floats (256 threads = 8 warps)
// ---------------------------------------------------------------------------
__device__ __forceinline__ void blockReduce2(float& a, float& b, float* sh) {
#pragma unroll
    for (int o = 16; o; o >>= 1) {
        a += __shfl_xor_sync(0xffffffffu, a, o);
        b += __shfl_xor_sync(0xffffffffu, b, o);
    }
    int w = threadIdx.x >> 5;
    if ((threadIdx.x & 31) == 0) { sh[w] = a; sh[w + 8] = b; }
    __syncthreads();
    if (threadIdx.x == 0) {
        float sa = 0.f, sb = 0.f;
#pragma unroll
        for (int i = 0; i < 8; i++) { sa += sh[i]; sb += sh[i + 8]; }
        sh[16] = sa; sh[17] = sb;
    }
    __syncthreads();
    a = sh[16]; b = sh[17];
    __syncthreads();
}

// ---------------------------------------------------------------------------
// K0: round weights to tf32 (RN) once.
// ---------------------------------------------------------------------------
__global__ __launch_bounds__(256) void k_roundW(const float* __restrict__ in,
                                                float* __restrict__ out, int n4) {
    int i = blockIdx.x * 256 + threadIdx.x;
    if (i < n4) {
        float4 v = ((const float4*)in)[i];
        v.x = tf32r(v.x); v.y = tf32r(v.y); v.z = tf32r(v.z); v.w = tf32r(v.w);
        ((float4*)out)[i] = v;
    }
}

// ---------------------------------------------------------------------------
// K1: LayerNorm1 + window partition + third-scatter.
// Third 0 (red) written 3x into A_red (tf32-rounded); thirds 1/2 raw into g_gb.
// ---------------------------------------------------------------------------
__global__ __launch_bounds__(256) void k_ln1(const float* __restrict__ x,
                                             const float* __restrict__ g,
                                             const float* __restrict__ b) {
    __shared__ float sh[32];
    int r  = blockIdx.x;
    int bb = r >> 14;
    int l  = r & 16383;
    int hh = l >> 7, ww = l & 127;
    int win = (bb * 16 + (hh >> 3)) * 16 + (ww >> 3);
    int n   = (hh & 7) * 8 + (ww & 7);
    int w64 = win * 64 + n;

    const float* xr = x + (size_t)r * CDIM;
    int c0 = threadIdx.x, c1 = threadIdx.x + 256, c2 = threadIdx.x + 512;
    float v0 = xr[c0], v1 = xr[c1], v2 = xr[c2];
    float s  = v0 + v1 + v2;
    float sq = v0 * v0 + v1 * v1 + v2 * v2;
    blockReduce2(s, sq, sh);
    float mean = s * (1.f / 768.f);
    float var  = sq * (1.f / 768.f) - mean * mean;
    float rs   = rsqrtf(var + 1e-5f);

    float o0 = (v0 - mean) * rs * g[c0] + b[c0];
    float o1 = (v1 - mean) * rs * g[c1] + b[c1];
    float o2 = (v2 - mean) * rs * g[c2] + b[c2];

    int fbase = w64 * CDIM;
#pragma unroll
    for (int u = 0; u < 3; u++) {
        int c = (u == 0) ? c0 : (u == 1 ? c1 : c2);
        float v = (u == 0) ? o0 : (u == 1 ? o1 : o2);
        int f = fbase + c;
        int t = f >> 24, off = f & MASKQ;
        if (t == 0) {
            float vr = tf32r(v);
            g_Ared[off] = vr; g_Ared[off + QC] = vr; g_Ared[off + 2 * QC] = vr;
        } else if (t == 1) {
            g_gb[off] = v;
        } else {
            g_gb[QC + off] = v;
        }
    }
}

// ---------------------------------------------------------------------------
// K1b: A_q = tf32_round(green + blue), tiled x3.
// ---------------------------------------------------------------------------
__global__ __launch_bounds__(256) void k_prep() {
    int i = blockIdx.x * 256 + threadIdx.x;     // float4 index in [0, QC/4)
    const float4* gb4 = (const float4*)g_gb;
    float4* aq4 = (float4*)g_Aq;
    float4 gg = gb4[i];
    float4 bb = gb4[QC / 4 + i];
    float4 q = make_float4(tf32r(gg.x + bb.x), tf32r(gg.y + bb.y),
                           tf32r(gg.z + bb.z), tf32r(gg.w + bb.w));
    aq4[i] = q;
    aq4[QC / 4 + i] = q;
    aq4[2 * QC / 4 + i] = q;
}

// ---------------------------------------------------------------------------
// K2/K4: tf32 mma.sync GEMM.  C[M=65536, N] = A[M,768] * B[N,768]^T
// Block tile 128x128xK32, 8 warps (warp tile 64x32), 3-stage cp.async pipeline.
// SMEM rows padded to 36 floats -> conflict-free fragment gather.
// mode 0: QKV (gridx 0-5:Q from Aq, 6-11:K, 12-17:V from Ared; scatter q/k/v)
// mode 1: proj (A=Ared, out row-linear + bias -> outq)
// ---------------------------------------------------------------------------
#define NSTG 3
#define A_FLOATS (128 * 36)             // 4608 floats per A tile
#define STG_FLOATS (2 * A_FLOATS)       // 9216 floats = 36864 B per stage
#define GSMEM_BYTES (NSTG * STG_FLOATS * 4)   // 110592

__global__ __launch_bounds__(256, 1) void k_gemm_mma(
    const float* __restrict__ Aq, const float* __restrict__ Ared,
    const float* __restrict__ B, int mode, const float* __restrict__ bias,
    float* __restrict__ outq, float* __restrict__ outk, float* __restrict__ outv)
{
    extern __shared__ float sm[];
    const int tid = threadIdx.x;
    const int wid = tid >> 5, lane = tid & 31;
    const int g = lane >> 2, t = lane & 3;
    const int wm = (wid >> 2) * 64, wn = (wid & 3) * 32;
    const int n0 = blockIdx.x * 128, m0 = blockIdx.y * 128;

    int sec = 0;
    const float* Abase = Ared;
    if (mode == 0) { sec = blockIdx.x / 6; if (sec == 0) Abase = Aq; }

    // load coords: thread -> (row, 64B half-row)
    const int lrow  = tid >> 1;
    const int lhalf = (tid & 1) * 16;
    const float* aSrc = Abase + (size_t)(m0 + lrow) * CDIM + lhalf;
    const float* bSrc = B + (size_t)(n0 + lrow) * CDIM + lhalf;
    const uint32_t sbase = smem_u32(sm);
    const uint32_t aDst = sbase + (uint32_t)(lrow * 36 + lhalf) * 4u;
    const uint32_t bDst = sbase + (uint32_t)(A_FLOATS + lrow * 36 + lhalf) * 4u;

    float acc[4][4][4];
#pragma unroll
    for (int mt = 0; mt < 4; mt++)
#pragma unroll
        for (int nt = 0; nt < 4; nt++)
#pragma unroll
            for (int q = 0; q < 4; q++) acc[mt][nt][q] = 0.f;

    // prologue: stages 0,1
#pragma unroll
    for (int s = 0; s < NSTG - 1; s++) {
        uint32_t so = (uint32_t)(s * STG_FLOATS) * 4u;
        int k0 = s * 32;
#pragma unroll
        for (int c = 0; c < 4; c++) cp16(aDst + so + c * 16, aSrc + k0 + c * 4);
#pragma unroll
        for (int c = 0; c < 4; c++) cp16(bDst + so + c * 16, bSrc + k0 + c * 4);
        CP_COMMIT();
    }

    for (int i = 0; i < 24; i++) {
        CP_WAIT1();
        __syncthreads();

        int j = i + NSTG - 1;
        if (j < 24) {
            uint32_t so = (uint32_t)((j % NSTG) * STG_FLOATS) * 4u;
            int k0 = j * 32;
#pragma unroll
            for (int c = 0; c < 4; c++) cp16(aDst + so + c * 16, aSrc + k0 + c * 4);
#pragma unroll
            for (int c = 0; c < 4; c++) cp16(bDst + so + c * 16, bSrc + k0 + c * 4);
            CP_COMMIT();
        }

        const int soA = (i % NSTG) * STG_FLOATS;
        const int soB = soA + A_FLOATS;
#pragma unroll
        for (int ks = 0; ks < 4; ks++) {
            uint32_t a[4][4], b[4][2];
#pragma unroll
            for (int mt = 0; mt < 4; mt++) {
                int r = wm + mt * 16 + g;
                a[mt][0] = __float_as_uint(sm[soA + r * 36 + ks * 8 + t]);
                a[mt][1] = __float_as_uint(sm[soA + (r + 8) * 36 + ks * 8 + t]);
                a[mt][2] = __float_as_uint(sm[soA + r * 36 + ks * 8 + t + 4]);
                a[mt][3] = __float_as_uint(sm[soA + (r + 8) * 36 + ks * 8 + t + 4]);
            }
#pragma unroll
            for (int nt = 0; nt < 4; nt++) {
                int rn = wn + nt * 8 + g;
                b[nt][0] = __float_as_uint(sm[soB + rn * 36 + ks * 8 + t]);
                b[nt][1] = __float_as_uint(sm[soB + rn * 36 + ks * 8 + t + 4]);
            }
#pragma unroll
            for (int mt = 0; mt < 4; mt++)
#pragma unroll
                for (int nt = 0; nt < 4; nt++)
                    mma_tf32(acc[mt][nt], a[mt], b[nt]);
        }
    }

    // Epilogue
    float* outp = outq;
    int colb = n0;
    if (mode == 0) {
        outp = (sec == 0) ? outq : (sec == 1 ? outk : outv);
        colb = n0 - sec * CDIM;
    }

#pragma unroll
    for (int mt = 0; mt < 4; mt++) {
        int r0 = m0 + wm + mt * 16 + g;
        int r1 = r0 + 8;
#pragma unroll
        for (int nt = 0; nt < 4; nt++) {
            int c = colb + wn + nt * 8 + 2 * t;
            if (mode == 0) {
                int head = c >> 6, d = c & 63;
                int w0 = r0 >> 6, nn0 = r0 & 63;
                int w1 = r1 >> 6, nn1 = r1 & 63;
                *(float2*)(outp + (size_t)w0 * 49152 + head * 4096 + nn0 * 64 + d) =
                    make_float2(acc[mt][nt][0], acc[mt][nt][1]);
                *(float2*)(outp + (size_t)w1 * 49152 + head * 4096 + nn1 * 64 + d) =
                    make_float2(acc[mt][nt][2], acc[mt][nt][3]);
            } else {
                float2 bv = *(const float2*)&bias[c];
                *(float2*)(outq + (size_t)r0 * CDIM + c) =
                    make_float2(acc[mt][nt][0] + bv.x, acc[mt][nt][1] + bv.y);
                *(float2*)(outq + (size_t)r1 * CDIM + c) =
                    make_float2(acc[mt][nt][2] + bv.x, acc[mt][nt][3] + bv.y);
            }
        }
    }
}

// ---------------------------------------------------------------------------
// K3: windowed attention, one block per (window, head). N=64, D=64.
// 4x4 register tiles, float4 shared loads. Output -> g_Ared (tf32-rounded).
// ---------------------------------------------------------------------------
__global__ __launch_bounds__(256) void k_attn() {
    __shared__ float bufA[64 * 68];   // q, then P
    __shared__ float bufB[64 * 68];   // k, then v
    const int wh = blockIdx.x;
    const float* qp = g_q + (size_t)wh * 4096;
    const float* kp = g_k + (size_t)wh * 4096;
    const float* vp = g_v + (size_t)wh * 4096;
    const int tid = threadIdx.x;
    const int tx = tid & 15, ty = tid >> 4;

#pragma unroll
    for (int u = 0; u < 16; u++) {
        int idx = tid + u * 256;
        int so  = (idx >> 6) * 68 + (idx & 63);
        bufA[so] = qp[idx];
        bufB[so] = kp[idx];
    }
    __syncthreads();

    float acc[4][4];
#pragma unroll
    for (int i = 0; i < 4; i++)
#pragma unroll
        for (int j = 0; j < 4; j++) acc[i][j] = 0.f;

#pragma unroll
    for (int c4 = 0; c4 < 16; c4++) {
        float4 qa[4], kb[4];
#pragma unroll
        for (int i = 0; i < 4; i++) qa[i] = *(const float4*)&bufA[(ty * 4 + i) * 68 + c4 * 4];
#pragma unroll
        for (int j = 0; j < 4; j++) kb[j] = *(const float4*)&bufB[(tx * 4 + j) * 68 + c4 * 4];
#pragma unroll
        for (int i = 0; i < 4; i++)
#pragma unroll
            for (int j = 0; j < 4; j++)
                acc[i][j] += qa[i].x * kb[j].x + qa[i].y * kb[j].y + qa[i].z * kb[j].z + qa[i].w * kb[j].w;
    }

#pragma unroll
    for (int i = 0; i < 4; i++) {
#pragma unroll
        for (int j = 0; j < 4; j++) acc[i][j] *= 0.125f;
        float m = fmaxf(fmaxf(acc[i][0], acc[i][1]), fmaxf(acc[i][2], acc[i][3]));
        m = fmaxf(m, __shfl_xor_sync(0xffffffffu, m, 1));
        m = fmaxf(m, __shfl_xor_sync(0xffffffffu, m, 2));
        m = fmaxf(m, __shfl_xor_sync(0xffffffffu, m, 4));
        m = fmaxf(m, __shfl_xor_sync(0xffffffffu, m, 8));
        float s = 0.f;
#pragma unroll
        for (int j = 0; j < 4; j++) { acc[i][j] = __expf(acc[i][j] - m); s += acc[i][j]; }
        s += __shfl_xor_sync(0xffffffffu, s, 1);
        s += __shfl_xor_sync(0xffffffffu, s, 2);
        s += __shfl_xor_sync(0xffffffffu, s, 4);
        s += __shfl_xor_sync(0xffffffffu, s, 8);
        float inv = 1.f / s;
#pragma unroll
        for (int j = 0; j < 4; j++) acc[i][j] *= inv;
    }

    __syncthreads();
#pragma unroll
    for (int i = 0; i < 4; i++)
        *(float4*)&bufA[(ty * 4 + i) * 68 + tx * 4] = make_float4(acc[i][0], acc[i][1], acc[i][2], acc[i][3]);
#pragma unroll
    for (int u = 0; u < 16; u++) {
        int idx = tid + u * 256;
        bufB[(idx >> 6) * 68 + (idx & 63)] = vp[idx];
    }
    __syncthreads();

    float o[4][4];
#pragma unroll
    for (int i = 0; i < 4; i++)
#pragma unroll
        for (int j = 0; j < 4; j++) o[i][j] = 0.f;

#pragma unroll
    for (int j4 = 0; j4 < 16; j4++) {
        float4 pa[4], vb[4];
#pragma unroll
        for (int i = 0; i < 4; i++)  pa[i] = *(const float4*)&bufA[(ty * 4 + i) * 68 + j4 * 4];
#pragma unroll
        for (int jj = 0; jj < 4; jj++) vb[jj] = *(const float4*)&bufB[(j4 * 4 + jj) * 68 + tx * 4];
#pragma unroll
        for (int i = 0; i < 4; i++) {
            o[i][0] += pa[i].x * vb[0].x + pa[i].y * vb[1].x + pa[i].z * vb[2].x + pa[i].w * vb[3].x;
            o[i][1] += pa[i].x * vb[0].y + pa[i].y * vb[1].y + pa[i].z * vb[2].y + pa[i].w * vb[3].y;
            o[i][2] += pa[i].x * vb[0].z + pa[i].y * vb[1].z + pa[i].z * vb[2].z + pa[i].w * vb[3].z;
            o[i][3] += pa[i].x * vb[0].w + pa[i].y * vb[1].w + pa[i].z * vb[2].w + pa[i].w * vb[3].w;
        }
    }

    const int win = wh / 12, head = wh % 12;
#pragma unroll
    for (int i = 0; i < 4; i++) {
        float* dst = g_Ared + (size_t)(win * 64 + ty * 4 + i) * CDIM + head * 64 + tx * 4;
        *(float4*)dst = make_float4(tf32r(o[i][0]), tf32r(o[i][1]), tf32r(o[i][2]), tf32r(o[i][3]));
    }
}

// ---------------------------------------------------------------------------
// K5: LN2 + fc1 (row dot) + exact GELU + fc2 (outer product) + biases.
// ---------------------------------------------------------------------------
__global__ __launch_bounds__(256) void k_final(const float* __restrict__ g2,
                                               const float* __restrict__ b2,
                                               const float* __restrict__ fc1w,
                                               const float* __restrict__ fc1b,
                                               const float* __restrict__ fc2w,
                                               const float* __restrict__ fc2b,
                                               float* __restrict__ out) {
    __shared__ float sh[32];
    int r = blockIdx.x;
    const float* pr = g_Aq + (size_t)r * CDIM;
    int c0 = threadIdx.x, c1 = threadIdx.x + 256, c2 = threadIdx.x + 512;
    float v0 = pr[c0], v1 = pr[c1], v2 = pr[c2];

    float s  = v0 + v1 + v2;
    float sq = v0 * v0 + v1 * v1 + v2 * v2;
    blockReduce2(s, sq, sh);
    float mean = s * (1.f / 768.f);
    float var  = sq * (1.f / 768.f) - mean * mean;
    float rs   = rsqrtf(var + 1e-5f);

    float a0 = (v0 - mean) * rs * g2[c0] + b2[c0];
    float a1 = (v1 - mean) * rs * g2[c1] + b2[c1];
    float a2 = (v2 - mean) * rs * g2[c2] + b2[c2];

    float dotp = a0 * fc1w[c0] + a1 * fc1w[c1] + a2 * fc1w[c2];
    float zero = 0.f;
    blockReduce2(dotp, zero, sh);
    float t  = dotp + fc1b[0];
    float hd = 0.5f * t * (1.f + erff(t * 0.70710678118654752f));

    float* orow = out + (size_t)r * CDIM;
    orow[c0] = hd * fc2w[c0] + fc2b[c0];
    orow[c1] = hd * fc2w[c1] + fc2b[c1];
    orow[c2] = hd * fc2w[c2] + fc2b[c2];
}

// ---------------------------------------------------------------------------
// Host side
// ---------------------------------------------------------------------------
extern "C" void kernel_launch(void* const* d_in, const int* in_sizes, int n_in,
                              void* d_out, int out_size) {
    const float* x     = (const float*)d_in[0];
    const float* n1g   = (const float*)d_in[1];
    const float* n1b   = (const float*)d_in[2];
    const float* n2g   = (const float*)d_in[3];
    const float* n2b   = (const float*)d_in[4];
    const float* qkvw  = (const float*)d_in[5];
    const float* projw = (const float*)d_in[6];
    const float* projb = (const float*)d_in[7];
    const float* fc1w  = (const float*)d_in[8];
    const float* fc1b  = (const float*)d_in[9];
    const float* fc2w  = (const float*)d_in[10];
    const float* fc2b  = (const float*)d_in[11];

    void *pAred, *pAq, *pQ, *pK, *pV, *pWqkv, *pWproj;
    cudaGetSymbolAddress(&pAred, g_Ared);
    cudaGetSymbolAddress(&pAq, g_Aq);
    cudaGetSymbolAddress(&pQ, g_q);
    cudaGetSymbolAddress(&pK, g_k);
    cudaGetSymbolAddress(&pV, g_v);
    cudaGetSymbolAddress(&pWqkv, g_Wqkv);
    cudaGetSymbolAddress(&pWproj, g_Wproj);

    static bool attrSet = false;
    if (!attrSet) {
        cudaFuncSetAttribute(k_gemm_mma, cudaFuncAttributeMaxDynamicSharedMemorySize, GSMEM_BYTES);
        attrSet = true;
    }

    // Round weights to tf32 (RN)
    k_roundW<<<(2304 * 768 / 4 + 255) / 256, 256>>>(qkvw, (float*)pWqkv, 2304 * 768 / 4);
    k_roundW<<<(768 * 768 / 4 + 255) / 256, 256>>>(projw, (float*)pWproj, 768 * 768 / 4);

    k_ln1<<<NROWS, 256>>>(x, n1g, n1b);
    k_prep<<<QC / 4 / 256, 256>>>();

    dim3 gq(18, 512);
    k_gemm_mma<<<gq, 256, GSMEM_BYTES>>>((const float*)pAq, (const float*)pAred,
                                         (const float*)pWqkv, 0, nullptr,
                                         (float*)pQ, (float*)pK, (float*)pV);

    k_attn<<<1024 * 12, 256>>>();

    dim3 gp(6, 512);
    k_gemm_mma<<<gp, 256, GSMEM_BYTES>>>((const float*)pAred, (const float*)pAred,
                                         (const float*)pWproj, 1, projb,
                                         (float*)pAq, nullptr, nullptr);

    k_final<<<NROWS, 256>>>(n2g, n2b, fc1w, fc1b, fc2w, fc2b, (float*)d_out);
}

// round 8
// speedup vs baseline: 4.4332x; 1.6671x over previous
#include <cuda_runtime.h>
#include <cuda_fp16.h>
#include <math.h>
#include <stdint.h>

// ---------------------------------------------------------------------------
// Problem constants
// ---------------------------------------------------------------------------
#define QC 16777216          // 2^24 = Bw*N*(C/3) — the tile() wrap period
#define MASKQ 0xFFFFFFu
#define NROWS 65536          // 1024 windows * 64 tokens
#define CDIM 768

// Scratch (device globals: allocation-free per harness rules)
__device__ __align__(16) __half g_Ah[QC];        // red third (half), wrap-indexed
__device__ __align__(16) __half g_Aqh[QC];       // green+blue third (half), wrap-indexed
__device__ __align__(16) float  g_gb[2 * QC];    // staging: green, blue thirds (fp32)
__device__ __align__(16) float  g_q[3 * QC];     // q (win, head, n, d) fp32
__device__ __align__(16) float  g_k[3 * QC];
__device__ __align__(16) float  g_v[3 * QC];
__device__ __align__(16) __half g_attnO[3 * QC]; // attention output (half), row-linear 65536x768
__device__ __align__(16) float  g_po[3 * QC];    // proj output fp32
__device__ __align__(16) __half g_Wqkvh[2304 * 768];
__device__ __align__(16) __half g_Wprojh[768 * 768];

// ---------------------------------------------------------------------------
// Helpers
// ---------------------------------------------------------------------------
__device__ __forceinline__ uint32_t smem_u32(const void* p) {
    uint32_t a;
    asm("{ .reg .u64 t; cvta.to.shared.u64 t, %1; cvt.u32.u64 %0, t; }" : "=r"(a) : "l"(p));
    return a;
}

__device__ __forceinline__ void cp16(uint32_t dst, const void* src) {
    asm volatile("cp.async.cg.shared.global [%0], [%1], 16;" :: "r"(dst), "l"(src));
}
#define CP_COMMIT() asm volatile("cp.async.commit_group;")
#define CP_WAIT1()  asm volatile("cp.async.wait_group 1;")

__device__ __forceinline__ void ldsm_x4(uint32_t* r, uint32_t addr) {
    asm volatile("ldmatrix.sync.aligned.m8n8.x4.shared.b16 {%0,%1,%2,%3}, [%4];"
        : "=r"(r[0]), "=r"(r[1]), "=r"(r[2]), "=r"(r[3]) : "r"(addr));
}

__device__ __forceinline__ void mma_f16(float* c, const uint32_t* a, const uint32_t* b) {
    asm volatile(
        "mma.sync.aligned.m16n8k16.row.col.f32.f16.f16.f32 "
        "{%0,%1,%2,%3}, {%4,%5,%6,%7}, {%8,%9}, {%0,%1,%2,%3};"
        : "+f"(c[0]), "+f"(c[1]), "+f"(c[2]), "+f"(c[3])
        : "r"(a[0]), "r"(a[1]), "r"(a[2]), "r"(a[3]), "r"(b[0]), "r"(b[1]));
}

// ---------------------------------------------------------------------------
// Block-wide reduction of two floats (256 threads = 8 warps)
// ---------------------------------------------------------------------------
__device__ __forceinline__ void blockReduce2(float& a, float& b, float* sh) {
#pragma unroll
    for (int o = 16; o; o >>= 1) {
        a += __shfl_xor_sync(0xffffffffu, a, o);
        b += __shfl_xor_sync(0xffffffffu, b, o);
    }
    int w = threadIdx.x >> 5;
    if ((threadIdx.x & 31) == 0) { sh[w] = a; sh[w + 8] = b; }
    __syncthreads();
    if (threadIdx.x == 0) {
        float sa = 0.f, sb = 0.f;
#pragma unroll
        for (int i = 0; i < 8; i++) { sa += sh[i]; sb += sh[i + 8]; }
        sh[16] = sa; sh[17] = sb;
    }
    __syncthreads();
    a = sh[16]; b = sh[17];
    __syncthreads();
}

// ---------------------------------------------------------------------------
// K0: convert weights to half (RN) once per call.
// ---------------------------------------------------------------------------
__global__ __launch_bounds__(256) void k_toHalf(const float* __restrict__ in,
                                                __half* __restrict__ out, int n4) {
    int i = blockIdx.x * 256 + threadIdx.x;
    if (i < n4) {
        float4 v = ((const float4*)in)[i];
        __half2 h0 = __floats2half2_rn(v.x, v.y);
        __half2 h1 = __floats2half2_rn(v.z, v.w);
        ((uint2*)out)[i] = make_uint2(*(uint32_t*)&h0, *(uint32_t*)&h1);
    }
}

// ---------------------------------------------------------------------------
// K1: LayerNorm1 + window partition + third-scatter.
// Third 0 (red) -> g_Ah (half, single copy); thirds 1/2 fp32 into g_gb.
// ---------------------------------------------------------------------------
__global__ __launch_bounds__(256) void k_ln1(const float* __restrict__ x,
                                             const float* __restrict__ g,
                                             const float* __restrict__ b) {
    __shared__ float sh[32];
    int r  = blockIdx.x;
    int bb = r >> 14;
    int l  = r & 16383;
    int hh = l >> 7, ww = l & 127;
    int win = (bb * 16 + (hh >> 3)) * 16 + (ww >> 3);
    int n   = (hh & 7) * 8 + (ww & 7);
    int w64 = win * 64 + n;

    const float* xr = x + (size_t)r * CDIM;
    int c0 = threadIdx.x, c1 = threadIdx.x + 256, c2 = threadIdx.x + 512;
    float v0 = xr[c0], v1 = xr[c1], v2 = xr[c2];
    float s  = v0 + v1 + v2;
    float sq = v0 * v0 + v1 * v1 + v2 * v2;
    blockReduce2(s, sq, sh);
    float mean = s * (1.f / 768.f);
    float var  = sq * (1.f / 768.f) - mean * mean;
    float rs   = rsqrtf(var + 1e-5f);

    float o0 = (v0 - mean) * rs * g[c0] + b[c0];
    float o1 = (v1 - mean) * rs * g[c1] + b[c1];
    float o2 = (v2 - mean) * rs * g[c2] + b[c2];

    int fbase = w64 * CDIM;
#pragma unroll
    for (int u = 0; u < 3; u++) {
        int c = (u == 0) ? c0 : (u == 1 ? c1 : c2);
        float v = (u == 0) ? o0 : (u == 1 ? o1 : o2);
        int f = fbase + c;
        int t = f >> 24, off = f & MASKQ;
        if (t == 0)      g_Ah[off] = __float2half_rn(v);
        else if (t == 1) g_gb[off] = v;
        else             g_gb[QC + off] = v;
    }
}

// ---------------------------------------------------------------------------
// K1b: A_q = half(green + blue), single copy.
// ---------------------------------------------------------------------------
__global__ __launch_bounds__(256) void k_prep() {
    int i = blockIdx.x * 256 + threadIdx.x;     // float4 index in [0, QC/4)
    const float4* gb4 = (const float4*)g_gb;
    float4 gg = gb4[i];
    float4 bb = gb4[QC / 4 + i];
    __half2 h0 = __floats2half2_rn(gg.x + bb.x, gg.y + bb.y);
    __half2 h1 = __floats2half2_rn(gg.z + bb.z, gg.w + bb.w);
    ((uint2*)g_Aqh)[i] = make_uint2(*(uint32_t*)&h0, *(uint32_t*)&h1);
}

// ---------------------------------------------------------------------------
// K2/K4: fp16 mma.sync GEMM.  C[M=65536, N] = A[M,768] * B[N,768]^T
// Block tile 128x128xK64, 8 warps (warp tile 64x32), 3-stage cp.async pipeline.
// A element index is (row*768+col) & mask  (mask = 0xFFFFFF for wrap, -1 plain).
// SMEM rows padded to 72 halfs (144B) -> conflict-free ldmatrix.
// mode 0: QKV (gridx 0-5: A=A0(Aq)->q; 6-11: A=A1(red)->k; 12-17: ->v; fp32 scatter)
// mode 1: proj (A=A0 plain, out row-linear fp32 + bias -> outq)
// ---------------------------------------------------------------------------
#define NSTG 3
#define LDH 72                         // halfs per smem row
#define TILE_H (128 * LDH)             // 9216 halfs per matrix tile
#define STG_H (2 * TILE_H)             // 18432 halfs per stage
#define GSMEM_BYTES (NSTG * STG_H * 2) // 110592 B

__global__ __launch_bounds__(256, 1) void k_gemm_h(
    const __half* __restrict__ A0, const __half* __restrict__ A1,
    const __half* __restrict__ B, uint32_t mask,
    int mode, const float* __restrict__ bias,
    float* __restrict__ outq, float* __restrict__ outk, float* __restrict__ outv)
{
    extern __shared__ __half smh[];
    const int tid = threadIdx.x;
    const int wid = tid >> 5, lane = tid & 31;
    const int g = lane >> 2, t = lane & 3;
    const int wm = (wid >> 2) * 64, wn = (wid & 3) * 32;
    const int n0 = blockIdx.x * 128, m0 = blockIdx.y * 128;

    int sec = 0;
    const __half* Abase = A0;
    if (mode == 0) { sec = blockIdx.x / 6; if (sec > 0) Abase = A1; }

    // loader mapping: thread -> (row, 32-half half-row)
    const int lrow = tid >> 1;
    const int lcol = (tid & 1) * 32;
    const uint32_t sbase = smem_u32(smh);
    const uint32_t aDst = sbase + (uint32_t)(lrow * LDH + lcol) * 2u;
    const uint32_t bDst = aDst + TILE_H * 2u;
    const uint32_t aGbase = (uint32_t)(m0 + lrow) * 768u + lcol;
    const __half* bSrc = B + (size_t)(n0 + lrow) * 768 + lcol;

    float acc[4][4][4];
#pragma unroll
    for (int mt = 0; mt < 4; mt++)
#pragma unroll
        for (int nt = 0; nt < 4; nt++)
#pragma unroll
            for (int q = 0; q < 4; q++) acc[mt][nt][q] = 0.f;

    // prologue: stages 0,1  (K chunks of 64)
#pragma unroll
    for (int s = 0; s < NSTG - 1; s++) {
        uint32_t so = (uint32_t)(s * STG_H) * 2u;
        uint32_t k0 = s * 64;
#pragma unroll
        for (int c = 0; c < 4; c++) cp16(aDst + so + c * 16, Abase + ((aGbase + k0 + c * 8) & mask));
#pragma unroll
        for (int c = 0; c < 4; c++) cp16(bDst + so + c * 16, bSrc + k0 + c * 8);
        CP_COMMIT();
    }

    // ldmatrix lane addressing
    const int lrA = lane & 15, lcA = (lane >> 4) * 8;
    const int lrB = (lane & 7) + ((lane >> 4) << 3), lcB = ((lane >> 3) & 1) * 8;

    for (int i = 0; i < 12; i++) {
        CP_WAIT1();
        __syncthreads();

        int j = i + NSTG - 1;
        if (j < 12) {
            uint32_t so = (uint32_t)((j % NSTG) * STG_H) * 2u;
            uint32_t k0 = j * 64;
#pragma unroll
            for (int c = 0; c < 4; c++) cp16(aDst + so + c * 16, Abase + ((aGbase + k0 + c * 8) & mask));
#pragma unroll
            for (int c = 0; c < 4; c++) cp16(bDst + so + c * 16, bSrc + k0 + c * 8);
            CP_COMMIT();
        }

        const uint32_t smA = sbase + (uint32_t)((i % NSTG) * STG_H) * 2u;
        const uint32_t smB = smA + TILE_H * 2u;
#pragma unroll
        for (int ks = 0; ks < 4; ks++) {
            uint32_t a[4][4], b[2][4];
#pragma unroll
            for (int mt = 0; mt < 4; mt++)
                ldsm_x4(a[mt], smA + (uint32_t)((wm + mt * 16 + lrA) * LDH + ks * 16 + lcA) * 2u);
#pragma unroll
            for (int ntp = 0; ntp < 2; ntp++)
                ldsm_x4(b[ntp], smB + (uint32_t)((wn + ntp * 16 + lrB) * LDH + ks * 16 + lcB) * 2u);
#pragma unroll
            for (int mt = 0; mt < 4; mt++)
#pragma unroll
                for (int nt = 0; nt < 4; nt++)
                    mma_f16(acc[mt][nt], a[mt], &b[nt >> 1][(nt & 1) * 2]);
        }
        __syncthreads();
    }

    // Epilogue
    float* outp = outq;
    int colb = n0;
    if (mode == 0) {
        outp = (sec == 0) ? outq : (sec == 1 ? outk : outv);
        colb = n0 - sec * CDIM;
    }

#pragma unroll
    for (int mt = 0; mt < 4; mt++) {
        int r0 = m0 + wm + mt * 16 + g;
        int r1 = r0 + 8;
#pragma unroll
        for (int nt = 0; nt < 4; nt++) {
            int c = colb + wn + nt * 8 + 2 * t;
            if (mode == 0) {
                int head = c >> 6, d = c & 63;
                int w0 = r0 >> 6, nn0 = r0 & 63;
                int w1 = r1 >> 6, nn1 = r1 & 63;
                *(float2*)(outp + (size_t)w0 * 49152 + head * 4096 + nn0 * 64 + d) =
                    make_float2(acc[mt][nt][0], acc[mt][nt][1]);
                *(float2*)(outp + (size_t)w1 * 49152 + head * 4096 + nn1 * 64 + d) =
                    make_float2(acc[mt][nt][2], acc[mt][nt][3]);
            } else {
                float2 bv = *(const float2*)&bias[c];
                *(float2*)(outq + (size_t)r0 * CDIM + c) =
                    make_float2(acc[mt][nt][0] + bv.x, acc[mt][nt][1] + bv.y);
                *(float2*)(outq + (size_t)r1 * CDIM + c) =
                    make_float2(acc[mt][nt][2] + bv.x, acc[mt][nt][3] + bv.y);
            }
        }
    }
}

// ---------------------------------------------------------------------------
// K3: windowed attention, one block per (window, head). N=64, D=64.
// fp32 SIMT; output stored as half into g_attnO (row-linear 65536x768).
// ---------------------------------------------------------------------------
__global__ __launch_bounds__(256) void k_attn() {
    __shared__ float bufA[64 * 68];   // q, then P
    __shared__ float bufB[64 * 68];   // k, then v
    const int wh = blockIdx.x;
    const float* qp = g_q + (size_t)wh * 4096;
    const float* kp = g_k + (size_t)wh * 4096;
    const float* vp = g_v + (size_t)wh * 4096;
    const int tid = threadIdx.x;
    const int tx = tid & 15, ty = tid >> 4;

#pragma unroll
    for (int u = 0; u < 16; u++) {
        int idx = tid + u * 256;
        int so  = (idx >> 6) * 68 + (idx & 63);
        bufA[so] = qp[idx];
        bufB[so] = kp[idx];
    }
    __syncthreads();

    float acc[4][4];
#pragma unroll
    for (int i = 0; i < 4; i++)
#pragma unroll
        for (int j = 0; j < 4; j++) acc[i][j] = 0.f;

#pragma unroll
    for (int c4 = 0; c4 < 16; c4++) {
        float4 qa[4], kb[4];
#pragma unroll
        for (int i = 0; i < 4; i++) qa[i] = *(const float4*)&bufA[(ty * 4 + i) * 68 + c4 * 4];
#pragma unroll
        for (int j = 0; j < 4; j++) kb[j] = *(const float4*)&bufB[(tx * 4 + j) * 68 + c4 * 4];
#pragma unroll
        for (int i = 0; i < 4; i++)
#pragma unroll
            for (int j = 0; j < 4; j++)
                acc[i][j] += qa[i].x * kb[j].x + qa[i].y * kb[j].y + qa[i].z * kb[j].z + qa[i].w * kb[j].w;
    }

#pragma unroll
    for (int i = 0; i < 4; i++) {
#pragma unroll
        for (int j = 0; j < 4; j++) acc[i][j] *= 0.125f;
        float m = fmaxf(fmaxf(acc[i][0], acc[i][1]), fmaxf(acc[i][2], acc[i][3]));
        m = fmaxf(m, __shfl_xor_sync(0xffffffffu, m, 1));
        m = fmaxf(m, __shfl_xor_sync(0xffffffffu, m, 2));
        m = fmaxf(m, __shfl_xor_sync(0xffffffffu, m, 4));
        m = fmaxf(m, __shfl_xor_sync(0xffffffffu, m, 8));
        float s = 0.f;
#pragma unroll
        for (int j = 0; j < 4; j++) { acc[i][j] = __expf(acc[i][j] - m); s += acc[i][j]; }
        s += __shfl_xor_sync(0xffffffffu, s, 1);
        s += __shfl_xor_sync(0xffffffffu, s, 2);
        s += __shfl_xor_sync(0xffffffffu, s, 4);
        s += __shfl_xor_sync(0xffffffffu, s, 8);
        float inv = 1.f / s;
#pragma unroll
        for (int j = 0; j < 4; j++) acc[i][j] *= inv;
    }

    __syncthreads();
#pragma unroll
    for (int i = 0; i < 4; i++)
        *(float4*)&bufA[(ty * 4 + i) * 68 + tx * 4] = make_float4(acc[i][0], acc[i][1], acc[i][2], acc[i][3]);
#pragma unroll
    for (int u = 0; u < 16; u++) {
        int idx = tid + u * 256;
        bufB[(idx >> 6) * 68 + (idx & 63)] = vp[idx];
    }
    __syncthreads();

    float o[4][4];
#pragma unroll
    for (int i = 0; i < 4; i++)
#pragma unroll
        for (int j = 0; j < 4; j++) o[i][j] = 0.f;

#pragma unroll
    for (int j4 = 0; j4 < 16; j4++) {
        float4 pa[4], vb[4];
#pragma unroll
        for (int i = 0; i < 4; i++)  pa[i] = *(const float4*)&bufA[(ty * 4 + i) * 68 + j4 * 4];
#pragma unroll
        for (int jj = 0; jj < 4; jj++) vb[jj] = *(const float4*)&bufB[(j4 * 4 + jj) * 68 + tx * 4];
#pragma unroll
        for (int i = 0; i < 4; i++) {
            o[i][0] += pa[i].x * vb[0].x + pa[i].y * vb[1].x + pa[i].z * vb[2].x + pa[i].w * vb[3].x;
            o[i][1] += pa[i].x * vb[0].y + pa[i].y * vb[1].y + pa[i].z * vb[2].y + pa[i].w * vb[3].y;
            o[i][2] += pa[i].x * vb[0].z + pa[i].y * vb[1].z + pa[i].z * vb[2].z + pa[i].w * vb[3].z;
            o[i][3] += pa[i].x * vb[0].w + pa[i].y * vb[1].w + pa[i].z * vb[2].w + pa[i].w * vb[3].w;
        }
    }

    const int win = wh / 12, head = wh % 12;
#pragma unroll
    for (int i = 0; i < 4; i++) {
        __half* dst = g_attnO + (size_t)(win * 64 + ty * 4 + i) * CDIM + head * 64 + tx * 4;
        __half2 h0 = __floats2half2_rn(o[i][0], o[i][1]);
        __half2 h1 = __floats2half2_rn(o[i][2], o[i][3]);
        *(uint2*)dst = make_uint2(*(uint32_t*)&h0, *(uint32_t*)&h1);
    }
}

// ---------------------------------------------------------------------------
// K5: LN2 + fc1 (row dot) + exact GELU + fc2 (outer product) + biases.
// ---------------------------------------------------------------------------
__global__ __launch_bounds__(256) void k_final(const float* __restrict__ g2,
                                               const float* __restrict__ b2,
                                               const float* __restrict__ fc1w,
                                               const float* __restrict__ fc1b,
                                               const float* __restrict__ fc2w,
                                               const float* __restrict__ fc2b,
                                               float* __restrict__ out) {
    __shared__ float sh[32];
    int r = blockIdx.x;
    const float* pr = g_po + (size_t)r * CDIM;
    int c0 = threadIdx.x, c1 = threadIdx.x + 256, c2 = threadIdx.x + 512;
    float v0 = pr[c0], v1 = pr[c1], v2 = pr[c2];

    float s  = v0 + v1 + v2;
    float sq = v0 * v0 + v1 * v1 + v2 * v2;
    blockReduce2(s, sq, sh);
    float mean = s * (1.f / 768.f);
    float var  = sq * (1.f / 768.f) - mean * mean;
    float rs   = rsqrtf(var + 1e-5f);

    float a0 = (v0 - mean) * rs * g2[c0] + b2[c0];
    float a1 = (v1 - mean) * rs * g2[c1] + b2[c1];
    float a2 = (v2 - mean) * rs * g2[c2] + b2[c2];

    float dotp = a0 * fc1w[c0] + a1 * fc1w[c1] + a2 * fc1w[c2];
    float zero = 0.f;
    blockReduce2(dotp, zero, sh);
    float t  = dotp + fc1b[0];
    float hd = 0.5f * t * (1.f + erff(t * 0.70710678118654752f));

    float* orow = out + (size_t)r * CDIM;
    orow[c0] = hd * fc2w[c0] + fc2b[c0];
    orow[c1] = hd * fc2w[c1] + fc2b[c1];
    orow[c2] = hd * fc2w[c2] + fc2b[c2];
}

// ---------------------------------------------------------------------------
// Host side
// ---------------------------------------------------------------------------
extern "C" void kernel_launch(void* const* d_in, const int* in_sizes, int n_in,
                              void* d_out, int out_size) {
    const float* x     = (const float*)d_in[0];
    const float* n1g   = (const float*)d_in[1];
    const float* n1b   = (const float*)d_in[2];
    const float* n2g   = (const float*)d_in[3];
    const float* n2b   = (const float*)d_in[4];
    const float* qkvw  = (const float*)d_in[5];
    const float* projw = (const float*)d_in[6];
    const float* projb = (const float*)d_in[7];
    const float* fc1w  = (const float*)d_in[8];
    const float* fc1b  = (const float*)d_in[9];
    const float* fc2w  = (const float*)d_in[10];
    const float* fc2b  = (const float*)d_in[11];

    void *pAh, *pAqh, *pQ, *pK, *pV, *pAO, *pPO, *pWq, *pWp;
    cudaGetSymbolAddress(&pAh, g_Ah);
    cudaGetSymbolAddress(&pAqh, g_Aqh);
    cudaGetSymbolAddress(&pQ, g_q);
    cudaGetSymbolAddress(&pK, g_k);
    cudaGetSymbolAddress(&pV, g_v);
    cudaGetSymbolAddress(&pAO, g_attnO);
    cudaGetSymbolAddress(&pPO, g_po);
    cudaGetSymbolAddress(&pWq, g_Wqkvh);
    cudaGetSymbolAddress(&pWp, g_Wprojh);

    static bool attrSet = false;
    if (!attrSet) {
        cudaFuncSetAttribute(k_gemm_h, cudaFuncAttributeMaxDynamicSharedMemorySize, GSMEM_BYTES);
        attrSet = true;
    }

    k_toHalf<<<2304 * 768 / 4 / 256, 256>>>(qkvw, (__half*)pWq, 2304 * 768 / 4);
    k_toHalf<<<768 * 768 / 4 / 256, 256>>>(projw, (__half*)pWp, 768 * 768 / 4);

    k_ln1<<<NROWS, 256>>>(x, n1g, n1b);
    k_prep<<<QC / 4 / 256, 256>>>();

    dim3 gq(18, 512);
    k_gemm_h<<<gq, 256, GSMEM_BYTES>>>((const __half*)pAqh, (const __half*)pAh,
                                       (const __half*)pWq, MASKQ, 0, nullptr,
                                       (float*)pQ, (float*)pK, (float*)pV);

    k_attn<<<1024 * 12, 256>>>();

    dim3 gp(6, 512);
    k_gemm_h<<<gp, 256, GSMEM_BYTES>>>((const __half*)pAO, (const __half*)pAO,
                                       (const __half*)pWp, 0xFFFFFFFFu, 1, projb,
                                       (float*)pPO, nullptr, nullptr);

    k_final<<<NROWS, 256>>>(n2g, n2b, fc1w, fc1b, fc2w, fc2b, (float*)d_out);
}

// round 11
// speedup vs baseline: 5.5821x; 1.2592x over previous
#include <cuda_runtime.h>
#include <cuda_fp16.h>
#include <math.h>
#include <stdint.h>

// ---------------------------------------------------------------------------
// Problem constants
// ---------------------------------------------------------------------------
#define QC 16777216          // 2^24 = Bw*N*(C/3) — the tile() wrap period
#define MASKQ 0xFFFFFFu
#define NROWS 65536          // 1024 windows * 64 tokens
#define CDIM 768

// Scratch (device globals: allocation-free per harness rules)
__device__ __align__(16) __half g_Ah[QC];        // red third (half), wrap-indexed
__device__ __align__(16) __half g_Aqh[QC];       // green+blue third (half), wrap-indexed
__device__ __align__(16) __half g_gbh[2 * QC];   // staging: green, blue thirds (half)
__device__ __align__(16) __half g_qh[3 * QC];    // q (win, head, n, d) half
__device__ __align__(16) __half g_kh[3 * QC];    // k
__device__ __align__(16) __half g_vh[3 * QC];    // v
__device__ __align__(16) __half g_attnO[3 * QC]; // attention output (half), row-linear 65536x768
__device__ __align__(16) float  g_po[3 * QC];    // proj output fp32
__device__ __align__(16) __half g_Wqkvh[2304 * 768];
__device__ __align__(16) __half g_Wprojh[768 * 768];

// ---------------------------------------------------------------------------
// Helpers
// ---------------------------------------------------------------------------
__device__ __forceinline__ uint32_t smem_u32(const void* p) {
    uint32_t a;
    asm("{ .reg .u64 t; cvta.to.shared.u64 t, %1; cvt.u32.u64 %0, t; }" : "=r"(a) : "l"(p));
    return a;
}

__device__ __forceinline__ void cp16(uint32_t dst, const void* src) {
    asm volatile("cp.async.cg.shared.global [%0], [%1], 16;" :: "r"(dst), "l"(src));
}
#define CP_COMMIT() asm volatile("cp.async.commit_group;")
#define CP_WAIT1()  asm volatile("cp.async.wait_group 1;")

__device__ __forceinline__ void ldsm_x4(uint32_t* r, uint32_t addr) {
    asm volatile("ldmatrix.sync.aligned.m8n8.x4.shared.b16 {%0,%1,%2,%3}, [%4];"
        : "=r"(r[0]), "=r"(r[1]), "=r"(r[2]), "=r"(r[3]) : "r"(addr));
}

__device__ __forceinline__ void ldsm_x4_t(uint32_t* r, uint32_t addr) {
    asm volatile("ldmatrix.sync.aligned.m8n8.x4.trans.shared.b16 {%0,%1,%2,%3}, [%4];"
        : "=r"(r[0]), "=r"(r[1]), "=r"(r[2]), "=r"(r[3]) : "r"(addr));
}

__device__ __forceinline__ void mma_f16(float* c, const uint32_t* a, const uint32_t* b) {
    asm volatile(
        "mma.sync.aligned.m16n8k16.row.col.f32.f16.f16.f32 "
        "{%0,%1,%2,%3}, {%4,%5,%6,%7}, {%8,%9}, {%0,%1,%2,%3};"
        : "+f"(c[0]), "+f"(c[1]), "+f"(c[2]), "+f"(c[3])
        : "r"(a[0]), "r"(a[1]), "r"(a[2]), "r"(a[3]), "r"(b[0]), "r"(b[1]));
}

__device__ __forceinline__ uint32_t packh2(float lo, float hi) {
    __half2 h = __floats2half2_rn(lo, hi);
    return *(uint32_t*)&h;
}

// ---------------------------------------------------------------------------
// Block-wide reduction of two floats (256 threads = 8 warps)
// ---------------------------------------------------------------------------
__device__ __forceinline__ void blockReduce2(float& a, float& b, float* sh) {
#pragma unroll
    for (int o = 16; o; o >>= 1) {
        a += __shfl_xor_sync(0xffffffffu, a, o);
        b += __shfl_xor_sync(0xffffffffu, b, o);
    }
    int w = threadIdx.x >> 5;
    if ((threadIdx.x & 31) == 0) { sh[w] = a; sh[w + 8] = b; }
    __syncthreads();
    if (threadIdx.x == 0) {
        float sa = 0.f, sb = 0.f;
#pragma unroll
        for (int i = 0; i < 8; i++) { sa += sh[i]; sb += sh[i + 8]; }
        sh[16] = sa; sh[17] = sb;
    }
    __syncthreads();
    a = sh[16]; b = sh[17];
    __syncthreads();
}

// ---------------------------------------------------------------------------
// K0: convert weights to half (RN).
// ---------------------------------------------------------------------------
__global__ __launch_bounds__(256) void k_toHalf(const float* __restrict__ in,
                                                __half* __restrict__ out, int n4) {
    int i = blockIdx.x * 256 + threadIdx.x;
    if (i < n4) {
        float4 v = ((const float4*)in)[i];
        __half2 h0 = __floats2half2_rn(v.x, v.y);
        __half2 h1 = __floats2half2_rn(v.z, v.w);
        ((uint2*)out)[i] = make_uint2(*(uint32_t*)&h0, *(uint32_t*)&h1);
    }
}

// ---------------------------------------------------------------------------
// K1: LayerNorm1 + window partition + third-scatter (all outputs half).
// ---------------------------------------------------------------------------
__global__ __launch_bounds__(256) void k_ln1(const float* __restrict__ x,
                                             const float* __restrict__ g,
                                             const float* __restrict__ b) {
    __shared__ float sh[32];
    int r  = blockIdx.x;
    int bb = r >> 14;
    int l  = r & 16383;
    int hh = l >> 7, ww = l & 127;
    int win = (bb * 16 + (hh >> 3)) * 16 + (ww >> 3);
    int n   = (hh & 7) * 8 + (ww & 7);
    int w64 = win * 64 + n;

    const float* xr = x + (size_t)r * CDIM;
    int c0 = threadIdx.x, c1 = threadIdx.x + 256, c2 = threadIdx.x + 512;
    float v0 = xr[c0], v1 = xr[c1], v2 = xr[c2];
    float s  = v0 + v1 + v2;
    float sq = v0 * v0 + v1 * v1 + v2 * v2;
    blockReduce2(s, sq, sh);
    float mean = s * (1.f / 768.f);
    float var  = sq * (1.f / 768.f) - mean * mean;
    float rs   = rsqrtf(var + 1e-5f);

    float o0 = (v0 - mean) * rs * g[c0] + b[c0];
    float o1 = (v1 - mean) * rs * g[c1] + b[c1];
    float o2 = (v2 - mean) * rs * g[c2] + b[c2];

    int fbase = w64 * CDIM;
#pragma unroll
    for (int u = 0; u < 3; u++) {
        int c = (u == 0) ? c0 : (u == 1 ? c1 : c2);
        float v = (u == 0) ? o0 : (u == 1 ? o1 : o2);
        int f = fbase + c;
        int t = f >> 24, off = f & MASKQ;
        if (t == 0)      g_Ah[off]       = __float2half_rn(v);
        else if (t == 1) g_gbh[off]      = __float2half_rn(v);
        else             g_gbh[QC + off] = __float2half_rn(v);
    }
}

// ---------------------------------------------------------------------------
// K1b: A_q = green + blue (half add).
// ---------------------------------------------------------------------------
__global__ __launch_bounds__(256) void k_prep() {
    int i = blockIdx.x * 256 + threadIdx.x;     // uint2 index (4 halfs), QC/4 total
    uint2 a = ((const uint2*)g_gbh)[i];
    uint2 b = ((const uint2*)(g_gbh + QC))[i];
    __half2 r0 = __hadd2(*(__half2*)&a.x, *(__half2*)&b.x);
    __half2 r1 = __hadd2(*(__half2*)&a.y, *(__half2*)&b.y);
    ((uint2*)g_Aqh)[i] = make_uint2(*(uint32_t*)&r0, *(uint32_t*)&r1);
}

// ---------------------------------------------------------------------------
// K2/K4: fp16 mma.sync GEMM.  C[M=65536, N] = A[M,768] * B[N,768]^T
// Block tile 128x128xK64, 8 warps, 3-stage cp.async.
// mode 0: QKV -> scatter q/k/v as HALF (win, head, n, d).
// mode 1: proj -> row-linear fp32 + bias.
// ---------------------------------------------------------------------------
#define NSTG 3
#define LDH 72                         // halfs per smem row
#define TILE_H (128 * LDH)
#define STG_H (2 * TILE_H)
#define GSMEM_BYTES (NSTG * STG_H * 2) // 110592 B

__global__ __launch_bounds__(256, 1) void k_gemm_h(
    const __half* __restrict__ A0, const __half* __restrict__ A1,
    const __half* __restrict__ B, uint32_t mask,
    int mode, const float* __restrict__ bias,
    __half* __restrict__ hq, __half* __restrict__ hk, __half* __restrict__ hv,
    float* __restrict__ outf)
{
    extern __shared__ __half smh[];
    const int tid = threadIdx.x;
    const int wid = tid >> 5, lane = tid & 31;
    const int g = lane >> 2, t = lane & 3;
    const int wm = (wid >> 2) * 64, wn = (wid & 3) * 32;
    const int n0 = blockIdx.x * 128, m0 = blockIdx.y * 128;

    int sec = 0;
    const __half* Abase = A0;
    if (mode == 0) { sec = blockIdx.x / 6; if (sec > 0) Abase = A1; }

    const int lrow = tid >> 1;
    const int lcol = (tid & 1) * 32;
    const uint32_t sbase = smem_u32(smh);
    const uint32_t aDst = sbase + (uint32_t)(lrow * LDH + lcol) * 2u;
    const uint32_t bDst = aDst + TILE_H * 2u;
    const uint32_t aGbase = (uint32_t)(m0 + lrow) * 768u + lcol;
    const __half* bSrc = B + (size_t)(n0 + lrow) * 768 + lcol;

    float acc[4][4][4];
#pragma unroll
    for (int mt = 0; mt < 4; mt++)
#pragma unroll
        for (int nt = 0; nt < 4; nt++)
#pragma unroll
            for (int q = 0; q < 4; q++) acc[mt][nt][q] = 0.f;

#pragma unroll
    for (int s = 0; s < NSTG - 1; s++) {
        uint32_t so = (uint32_t)(s * STG_H) * 2u;
        uint32_t k0 = s * 64;
#pragma unroll
        for (int c = 0; c < 4; c++) cp16(aDst + so + c * 16, Abase + ((aGbase + k0 + c * 8) & mask));
#pragma unroll
        for (int c = 0; c < 4; c++) cp16(bDst + so + c * 16, bSrc + k0 + c * 8);
        CP_COMMIT();
    }

    const int lrA = lane & 15, lcA = (lane >> 4) * 8;
    const int lrB = (lane & 7) + ((lane >> 4) << 3), lcB = ((lane >> 3) & 1) * 8;

    for (int i = 0; i < 12; i++) {
        CP_WAIT1();
        __syncthreads();

        int j = i + NSTG - 1;
        if (j < 12) {
            uint32_t so = (uint32_t)((j % NSTG) * STG_H) * 2u;
            uint32_t k0 = j * 64;
#pragma unroll
            for (int c = 0; c < 4; c++) cp16(aDst + so + c * 16, Abase + ((aGbase + k0 + c * 8) & mask));
#pragma unroll
            for (int c = 0; c < 4; c++) cp16(bDst + so + c * 16, bSrc + k0 + c * 8);
            CP_COMMIT();
        }

        const uint32_t smA = sbase + (uint32_t)((i % NSTG) * STG_H) * 2u;
        const uint32_t smB = smA + TILE_H * 2u;
#pragma unroll
        for (int ks = 0; ks < 4; ks++) {
            uint32_t a[4][4], b[2][4];
#pragma unroll
            for (int mt = 0; mt < 4; mt++)
                ldsm_x4(a[mt], smA + (uint32_t)((wm + mt * 16 + lrA) * LDH + ks * 16 + lcA) * 2u);
#pragma unroll
            for (int ntp = 0; ntp < 2; ntp++)
                ldsm_x4(b[ntp], smB + (uint32_t)((wn + ntp * 16 + lrB) * LDH + ks * 16 + lcB) * 2u);
#pragma unroll
            for (int mt = 0; mt < 4; mt++)
#pragma unroll
                for (int nt = 0; nt < 4; nt++)
                    mma_f16(acc[mt][nt], a[mt], &b[nt >> 1][(nt & 1) * 2]);
        }
        __syncthreads();
    }

    // Epilogue
    __half* outp = hq;
    int colb = n0;
    if (mode == 0) {
        outp = (sec == 0) ? hq : (sec == 1 ? hk : hv);
        colb = n0 - sec * CDIM;
    }

#pragma unroll
    for (int mt = 0; mt < 4; mt++) {
        int r0 = m0 + wm + mt * 16 + g;
        int r1 = r0 + 8;
#pragma unroll
        for (int nt = 0; nt < 4; nt++) {
            int c = colb + wn + nt * 8 + 2 * t;
            if (mode == 0) {
                int head = c >> 6, d = c & 63;
                int w0 = r0 >> 6, nn0 = r0 & 63;
                int w1 = r1 >> 6, nn1 = r1 & 63;
                *(uint32_t*)(outp + (size_t)w0 * 49152 + head * 4096 + nn0 * 64 + d) =
                    packh2(acc[mt][nt][0], acc[mt][nt][1]);
                *(uint32_t*)(outp + (size_t)w1 * 49152 + head * 4096 + nn1 * 64 + d) =
                    packh2(acc[mt][nt][2], acc[mt][nt][3]);
            } else {
                float2 bv = *(const float2*)&bias[c];
                *(float2*)(outf + (size_t)r0 * CDIM + c) =
                    make_float2(acc[mt][nt][0] + bv.x, acc[mt][nt][1] + bv.y);
                *(float2*)(outf + (size_t)r1 * CDIM + c) =
                    make_float2(acc[mt][nt][2] + bv.x, acc[mt][nt][3] + bv.y);
            }
        }
    }
}

// ---------------------------------------------------------------------------
// K3: tensor-core windowed attention. One block per (window, head), 128 thr.
// S = q k^T * 0.125 (fp32 acc), softmax on fragments, O = P v via trans-ldsm.
// Output half into g_attnO (row-linear 65536x768).
// ---------------------------------------------------------------------------
#define ALD 72   // smem row stride in halfs

__global__ __launch_bounds__(128) void k_attn_h() {
    __shared__ __half sq[64 * ALD], sk[64 * ALD], sv[64 * ALD];
    const int wh = blockIdx.x;                 // win*12 + head
    const __half* qp = g_qh + (size_t)wh * 4096;
    const __half* kp = g_kh + (size_t)wh * 4096;
    const __half* vp = g_vh + (size_t)wh * 4096;
    const int tid = threadIdx.x, wid = tid >> 5, lane = tid & 31;
    const int g = lane >> 2, t = lane & 3;

    // load q,k,v (each 4096 halfs = 512 uint4)
#pragma unroll
    for (int u = 0; u < 4; u++) {
        int li = tid + u * 128;
        int row = li >> 3, c8 = li & 7;
        *(uint4*)&sq[row * ALD + c8 * 8] = ((const uint4*)qp)[li];
        *(uint4*)&sk[row * ALD + c8 * 8] = ((const uint4*)kp)[li];
        *(uint4*)&sv[row * ALD + c8 * 8] = ((const uint4*)vp)[li];
    }
    __syncthreads();

    const uint32_t sbq = smem_u32(sq), sbk = smem_u32(sk), sbv = smem_u32(sv);
    const int lrA = lane & 15, lcA = (lane >> 4) * 8;
    const int lrB = (lane & 7) + ((lane >> 4) << 3), lcB = ((lane >> 3) & 1) * 8;

    // ---- S = q k^T  (warp owns rows wid*16..+15; full 64 cols in 8 n-tiles) ----
    float sacc[8][4];
#pragma unroll
    for (int nt = 0; nt < 8; nt++)
#pragma unroll
        for (int q = 0; q < 4; q++) sacc[nt][q] = 0.f;

#pragma unroll
    for (int ks = 0; ks < 4; ks++) {
        uint32_t a[4], b[4][4];
        ldsm_x4(a, sbq + (uint32_t)((wid * 16 + lrA) * ALD + ks * 16 + lcA) * 2u);
#pragma unroll
        for (int np = 0; np < 4; np++)
            ldsm_x4(b[np], sbk + (uint32_t)((np * 16 + lrB) * ALD + ks * 16 + lcB) * 2u);
#pragma unroll
        for (int nt = 0; nt < 8; nt++)
            mma_f16(sacc[nt], a, &b[nt >> 1][(nt & 1) * 2]);
    }

    // ---- softmax on fragments (rows g and g+8 of this warp's 16-row block) ----
    float mx0 = -1e30f, mx1 = -1e30f;
#pragma unroll
    for (int nt = 0; nt < 8; nt++) {
#pragma unroll
        for (int q = 0; q < 4; q++) sacc[nt][q] *= 0.125f;
        mx0 = fmaxf(mx0, fmaxf(sacc[nt][0], sacc[nt][1]));
        mx1 = fmaxf(mx1, fmaxf(sacc[nt][2], sacc[nt][3]));
    }
    mx0 = fmaxf(mx0, __shfl_xor_sync(0xffffffffu, mx0, 1));
    mx0 = fmaxf(mx0, __shfl_xor_sync(0xffffffffu, mx0, 2));
    mx1 = fmaxf(mx1, __shfl_xor_sync(0xffffffffu, mx1, 1));
    mx1 = fmaxf(mx1, __shfl_xor_sync(0xffffffffu, mx1, 2));

    float sum0 = 0.f, sum1 = 0.f;
#pragma unroll
    for (int nt = 0; nt < 8; nt++) {
        sacc[nt][0] = __expf(sacc[nt][0] - mx0);
        sacc[nt][1] = __expf(sacc[nt][1] - mx0);
        sacc[nt][2] = __expf(sacc[nt][2] - mx1);
        sacc[nt][3] = __expf(sacc[nt][3] - mx1);
        sum0 += sacc[nt][0] + sacc[nt][1];
        sum1 += sacc[nt][2] + sacc[nt][3];
    }
    sum0 += __shfl_xor_sync(0xffffffffu, sum0, 1);
    sum0 += __shfl_xor_sync(0xffffffffu, sum0, 2);
    sum1 += __shfl_xor_sync(0xffffffffu, sum1, 1);
    sum1 += __shfl_xor_sync(0xffffffffu, sum1, 2);

    // ---- pack P into A fragments: pa[kt] covers k-dim (j) = kt*16 .. +15 ----
    // A fragment layout for m16n8k16: regs {a0,a1,a2,a3} =
    //   a0 = (row g,   cols 2t,2t+1 of k-block lo8), a1 = (row g+8, same)
    //   a2 = (row g,   cols of k-block hi8),         a3 = (row g+8, hi8)
    // C fragment nt covers cols nt*8+2t, +1 rows g (c0,c1) and g+8 (c2,c3).
    // So S C-tiles 2kt (cols kt*16..+7) and 2kt+1 (cols kt*16+8..+15) map to:
    //   pa[kt][0] = packh2(sacc[2kt][0],   sacc[2kt][1])    row g,   lo8
    //   pa[kt][1] = packh2(sacc[2kt][2],   sacc[2kt][3])    row g+8, lo8
    //   pa[kt][2] = packh2(sacc[2kt+1][0], sacc[2kt+1][1])  row g,   hi8
    //   pa[kt][3] = packh2(sacc[2kt+1][2], sacc[2kt+1][3])  row g+8, hi8
    uint32_t pa[4][4];
#pragma unroll
    for (int kt = 0; kt < 4; kt++) {
        pa[kt][0] = packh2(sacc[2 * kt][0],     sacc[2 * kt][1]);
        pa[kt][1] = packh2(sacc[2 * kt][2],     sacc[2 * kt][3]);
        pa[kt][2] = packh2(sacc[2 * kt + 1][0], sacc[2 * kt + 1][1]);
        pa[kt][3] = packh2(sacc[2 * kt + 1][2], sacc[2 * kt + 1][3]);
    }

    // ---- O = P v  (v[j][d] via ldmatrix.trans: B operand n=d, k=j) ----
    float oacc[8][4];
#pragma unroll
    for (int nt = 0; nt < 8; nt++)
#pragma unroll
        for (int q = 0; q < 4; q++) oacc[nt][q] = 0.f;

    const int lrV = (lane & 7) + (((lane >> 3) & 1) << 3);
    const int lcV = (lane >> 4) * 8;
#pragma unroll
    for (int kt = 0; kt < 4; kt++) {
        uint32_t b[4][4];
#pragma unroll
        for (int dp = 0; dp < 4; dp++)
            ldsm_x4_t(b[dp], sbv + (uint32_t)((kt * 16 + lrV) * ALD + dp * 16 + lcV) * 2u);
#pragma unroll
        for (int nt = 0; nt < 8; nt++)
            mma_f16(oacc[nt], pa[kt], &b[nt >> 1][(nt & 1) * 2]);
    }

    // ---- epilogue: normalize by row-sum, store half ----
    const float inv0 = 1.f / sum0, inv1 = 1.f / sum1;
    const int win = wh / 12, head = wh % 12;
    const int r0 = wid * 16 + g;
    __half* dst0 = g_attnO + (size_t)(win * 64 + r0) * CDIM + head * 64;
    __half* dst1 = g_attnO + (size_t)(win * 64 + r0 + 8) * CDIM + head * 64;
#pragma unroll
    for (int nt = 0; nt < 8; nt++) {
        int c = nt * 8 + 2 * t;
        *(uint32_t*)(dst0 + c) = packh2(oacc[nt][0] * inv0, oacc[nt][1] * inv0);
        *(uint32_t*)(dst1 + c) = packh2(oacc[nt][2] * inv1, oacc[nt][3] * inv1);
    }
}

// ---------------------------------------------------------------------------
// K5: LN2 + fc1 (row dot) + exact GELU + fc2 (outer product) + biases.
// ---------------------------------------------------------------------------
__global__ __launch_bounds__(256) void k_final(const float* __restrict__ g2,
                                               const float* __restrict__ b2,
                                               const float* __restrict__ fc1w,
                                               const float* __restrict__ fc1b,
                                               const float* __restrict__ fc2w,
                                               const float* __restrict__ fc2b,
                                               float* __restrict__ out) {
    __shared__ float sh[32];
    int r = blockIdx.x;
    const float* pr = g_po + (size_t)r * CDIM;
    int c0 = threadIdx.x, c1 = threadIdx.x + 256, c2 = threadIdx.x + 512;
    float v0 = pr[c0], v1 = pr[c1], v2 = pr[c2];

    float s  = v0 + v1 + v2;
    float sq = v0 * v0 + v1 * v1 + v2 * v2;
    blockReduce2(s, sq, sh);
    float mean = s * (1.f / 768.f);
    float var  = sq * (1.f / 768.f) - mean * mean;
    float rs   = rsqrtf(var + 1e-5f);

    float a0 = (v0 - mean) * rs * g2[c0] + b2[c0];
    float a1 = (v1 - mean) * rs * g2[c1] + b2[c1];
    float a2 = (v2 - mean) * rs * g2[c2] + b2[c2];

    float dotp = a0 * fc1w[c0] + a1 * fc1w[c1] + a2 * fc1w[c2];
    float zero = 0.f;
    blockReduce2(dotp, zero, sh);
    float t  = dotp + fc1b[0];
    float hd = 0.5f * t * (1.f + erff(t * 0.70710678118654752f));

    float* orow = out + (size_t)r * CDIM;
    orow[c0] = hd * fc2w[c0] + fc2b[c0];
    orow[c1] = hd * fc2w[c1] + fc2b[c1];
    orow[c2] = hd * fc2w[c2] + fc2b[c2];
}

// ---------------------------------------------------------------------------
// Host side
// ---------------------------------------------------------------------------
extern "C" void kernel_launch(void* const* d_in, const int* in_sizes, int n_in,
                              void* d_out, int out_size) {
    const float* x     = (const float*)d_in[0];
    const float* n1g   = (const float*)d_in[1];
    const float* n1b   = (const float*)d_in[2];
    const float* n2g   = (const float*)d_in[3];
    const float* n2b   = (const float*)d_in[4];
    const float* qkvw  = (const float*)d_in[5];
    const float* projw = (const float*)d_in[6];
    const float* projb = (const float*)d_in[7];
    const float* fc1w  = (const float*)d_in[8];
    const float* fc1b  = (const float*)d_in[9];
    const float* fc2w  = (const float*)d_in[10];
    const float* fc2b  = (const float*)d_in[11];

    void *pAh, *pAqh, *pQ, *pK, *pV, *pAO, *pPO, *pWq, *pWp;
    cudaGetSymbolAddress(&pAh, g_Ah);
    cudaGetSymbolAddress(&pAqh, g_Aqh);
    cudaGetSymbolAddress(&pQ, g_qh);
    cudaGetSymbolAddress(&pK, g_kh);
    cudaGetSymbolAddress(&pV, g_vh);
    cudaGetSymbolAddress(&pAO, g_attnO);
    cudaGetSymbolAddress(&pPO, g_po);
    cudaGetSymbolAddress(&pWq, g_Wqkvh);
    cudaGetSymbolAddress(&pWp, g_Wprojh);

    static bool attrSet = false;
    if (!attrSet) {
        cudaFuncSetAttribute(k_gemm_h, cudaFuncAttributeMaxDynamicSharedMemorySize, GSMEM_BYTES);
        attrSet = true;
    }

    k_toHalf<<<2304 * 768 / 4 / 256, 256>>>(qkvw, (__half*)pWq, 2304 * 768 / 4);
    k_toHalf<<<768 * 768 / 4 / 256, 256>>>(projw, (__half*)pWp, 768 * 768 / 4);

    k_ln1<<<NROWS, 256>>>(x, n1g, n1b);
    k_prep<<<QC / 4 / 256, 256>>>();

    dim3 gq(18, 512);
    k_gemm_h<<<gq, 256, GSMEM_BYTES>>>((const __half*)pAqh, (const __half*)pAh,
                                       (const __half*)pWq, MASKQ, 0, nullptr,
                                       (__half*)pQ, (__half*)pK, (__half*)pV, nullptr);

    k_attn_h<<<1024 * 12, 128>>>();

    dim3 gp(6, 512);
    k_gemm_h<<<gp, 256, GSMEM_BYTES>>>((const __half*)pAO, (const __half*)pAO,
                                       (const __half*)pWp, 0xFFFFFFFFu, 1, projb,
                                       nullptr, nullptr, nullptr, (float*)pPO);

    k_final<<<NROWS, 256>>>(n2g, n2b, fc1w, fc1b, fc2w, fc2b, (float*)d_out);
}

// round 15
// speedup vs baseline: 5.9875x; 1.0726x over previous
#include <cuda_runtime.h>
#include <cuda_fp16.h>
#include <math.h>
#include <stdint.h>

// ---------------------------------------------------------------------------
// Problem constants
// ---------------------------------------------------------------------------
#define QC 16777216          // 2^24 = Bw*N*(C/3) — the tile() wrap period
#define MASKQ 0xFFFFFFu
#define NROWS 65536          // 1024 windows * 64 tokens
#define CDIM 768

// Scratch (device globals: allocation-free per harness rules)
__device__ __align__(16) __half g_Ah[QC];        // red third (half), wrap-indexed
__device__ __align__(16) __half g_Aqh[QC];       // green+blue third (half), wrap-indexed
__device__ __align__(16) __half g_gbh[2 * QC];   // staging: green, blue thirds (half)
__device__ __align__(16) __half g_qh[3 * QC];    // q (win, head, n, d) half
__device__ __align__(16) __half g_kh[3 * QC];    // k
__device__ __align__(16) __half g_vh[3 * QC];    // v
__device__ __align__(16) __half g_attnO[3 * QC]; // attention output (half), row-linear 65536x768
__device__ __align__(16) float  g_po[3 * QC];    // proj output fp32
__device__ __align__(16) __half g_Wqkvh[2304 * 768];
__device__ __align__(16) __half g_Wprojh[768 * 768];

// ---------------------------------------------------------------------------
// Helpers
// ---------------------------------------------------------------------------
__device__ __forceinline__ uint32_t smem_u32(const void* p) {
    uint32_t a;
    asm("{ .reg .u64 t; cvta.to.shared.u64 t, %1; cvt.u32.u64 %0, t; }" : "=r"(a) : "l"(p));
    return a;
}

__device__ __forceinline__ void cp16(uint32_t dst, const void* src) {
    asm volatile("cp.async.cg.shared.global [%0], [%1], 16;" :: "r"(dst), "l"(src));
}
#define CP_COMMIT() asm volatile("cp.async.commit_group;")
#define CP_WAIT1()  asm volatile("cp.async.wait_group 1;")

__device__ __forceinline__ void ldsm_x4(uint32_t* r, uint32_t addr) {
    asm volatile("ldmatrix.sync.aligned.m8n8.x4.shared.b16 {%0,%1,%2,%3}, [%4];"
        : "=r"(r[0]), "=r"(r[1]), "=r"(r[2]), "=r"(r[3]) : "r"(addr));
}

__device__ __forceinline__ void ldsm_x4_t(uint32_t* r, uint32_t addr) {
    asm volatile("ldmatrix.sync.aligned.m8n8.x4.trans.shared.b16 {%0,%1,%2,%3}, [%4];"
        : "=r"(r[0]), "=r"(r[1]), "=r"(r[2]), "=r"(r[3]) : "r"(addr));
}

__device__ __forceinline__ void mma_f16(float* c, const uint32_t* a, const uint32_t* b) {
    asm volatile(
        "mma.sync.aligned.m16n8k16.row.col.f32.f16.f16.f32 "
        "{%0,%1,%2,%3}, {%4,%5,%6,%7}, {%8,%9}, {%0,%1,%2,%3};"
        : "+f"(c[0]), "+f"(c[1]), "+f"(c[2]), "+f"(c[3])
        : "r"(a[0]), "r"(a[1]), "r"(a[2]), "r"(a[3]), "r"(b[0]), "r"(b[1]));
}

__device__ __forceinline__ uint32_t packh2(float lo, float hi) {
    __half2 h = __floats2half2_rn(lo, hi);
    return *(uint32_t*)&h;
}

// ---------------------------------------------------------------------------
// Block-wide reduction of two floats (256 threads = 8 warps)
// ---------------------------------------------------------------------------
__device__ __forceinline__ void blockReduce2(float& a, float& b, float* sh) {
#pragma unroll
    for (int o = 16; o; o >>= 1) {
        a += __shfl_xor_sync(0xffffffffu, a, o);
        b += __shfl_xor_sync(0xffffffffu, b, o);
    }
    int w = threadIdx.x >> 5;
    if ((threadIdx.x & 31) == 0) { sh[w] = a; sh[w + 8] = b; }
    __syncthreads();
    if (threadIdx.x == 0) {
        float sa = 0.f, sb = 0.f;
#pragma unroll
        for (int i = 0; i < 8; i++) { sa += sh[i]; sb += sh[i + 8]; }
        sh[16] = sa; sh[17] = sb;
    }
    __syncthreads();
    a = sh[16]; b = sh[17];
    __syncthreads();
}

// ---------------------------------------------------------------------------
// K0: convert weights to half (RN).
// ---------------------------------------------------------------------------
__global__ __launch_bounds__(256) void k_toHalf(const float* __restrict__ in,
                                                __half* __restrict__ out, int n4) {
    int i = blockIdx.x * 256 + threadIdx.x;
    if (i < n4) {
        float4 v = ((const float4*)in)[i];
        __half2 h0 = __floats2half2_rn(v.x, v.y);
        __half2 h1 = __floats2half2_rn(v.z, v.w);
        ((uint2*)out)[i] = make_uint2(*(uint32_t*)&h0, *(uint32_t*)&h1);
    }
}

// ---------------------------------------------------------------------------
// K1: LayerNorm1 + window partition + third-scatter (all outputs half).
// ---------------------------------------------------------------------------
__global__ __launch_bounds__(256) void k_ln1(const float* __restrict__ x,
                                             const float* __restrict__ g,
                                             const float* __restrict__ b) {
    __shared__ float sh[32];
    int r  = blockIdx.x;
    int bb = r >> 14;
    int l  = r & 16383;
    int hh = l >> 7, ww = l & 127;
    int win = (bb * 16 + (hh >> 3)) * 16 + (ww >> 3);
    int n   = (hh & 7) * 8 + (ww & 7);
    int w64 = win * 64 + n;

    const float* xr = x + (size_t)r * CDIM;
    int c0 = threadIdx.x, c1 = threadIdx.x + 256, c2 = threadIdx.x + 512;
    float v0 = xr[c0], v1 = xr[c1], v2 = xr[c2];
    float s  = v0 + v1 + v2;
    float sq = v0 * v0 + v1 * v1 + v2 * v2;
    blockReduce2(s, sq, sh);
    float mean = s * (1.f / 768.f);
    float var  = sq * (1.f / 768.f) - mean * mean;
    float rs   = rsqrtf(var + 1e-5f);

    float o0 = (v0 - mean) * rs * g[c0] + b[c0];
    float o1 = (v1 - mean) * rs * g[c1] + b[c1];
    float o2 = (v2 - mean) * rs * g[c2] + b[c2];

    int fbase = w64 * CDIM;
#pragma unroll
    for (int u = 0; u < 3; u++) {
        int c = (u == 0) ? c0 : (u == 1 ? c1 : c2);
        float v = (u == 0) ? o0 : (u == 1 ? o1 : o2);
        int f = fbase + c;
        int t = f >> 24, off = f & MASKQ;
        if (t == 0)      g_Ah[off]       = __float2half_rn(v);
        else if (t == 1) g_gbh[off]      = __float2half_rn(v);
        else             g_gbh[QC + off] = __float2half_rn(v);
    }
}

// ---------------------------------------------------------------------------
// K1b: A_q = green + blue (half add).
// ---------------------------------------------------------------------------
__global__ __launch_bounds__(256) void k_prep() {
    int i = blockIdx.x * 256 + threadIdx.x;     // uint2 index (4 halfs), QC/4 total
    uint2 a = ((const uint2*)g_gbh)[i];
    uint2 b = ((const uint2*)(g_gbh + QC))[i];
    __half2 r0 = __hadd2(*(__half2*)&a.x, *(__half2*)&b.x);
    __half2 r1 = __hadd2(*(__half2*)&a.y, *(__half2*)&b.y);
    ((uint2*)g_Aqh)[i] = make_uint2(*(uint32_t*)&r0, *(uint32_t*)&r1);
}

// ---------------------------------------------------------------------------
// K2/K4: fp16 mma.sync GEMM.  C[M=65536, N] = A[M,768] * B[N,768]^T
// Block tile 128(M) x 256(N) x K64, 8 warps (warp tile 64x64), 2-stage cp.async.
// A element index is (row*768+col) & mask  (0xFFFFFF wrap, or -1 plain).
// mode 0: QKV -> scatter q/k/v as HALF (win, head, n, d); gridx 0-2 Q, 3-5 K, 6-8 V.
// mode 1: proj -> row-linear fp32 + bias.
// ---------------------------------------------------------------------------
#define LDH 72                         // halfs per smem row
#define A_TILE_H (128 * LDH)           // 9216 halfs
#define B_TILE_H (256 * LDH)           // 18432 halfs
#define STG_H (A_TILE_H + B_TILE_H)    // 27648 halfs = 55296 B per stage
#define GSMEM_BYTES (2 * STG_H * 2)    // 110592 B

__global__ __launch_bounds__(256, 1) void k_gemm_h(
    const __half* __restrict__ A0, const __half* __restrict__ A1,
    const __half* __restrict__ B, uint32_t mask,
    int mode, const float* __restrict__ bias,
    __half* __restrict__ hq, __half* __restrict__ hk, __half* __restrict__ hv,
    float* __restrict__ outf)
{
    extern __shared__ __half smh[];
    const int tid = threadIdx.x;
    const int wid = tid >> 5, lane = tid & 31;
    const int g = lane >> 2, t = lane & 3;
    const int wm = (wid >> 2) * 64, wn = (wid & 3) * 64;
    const int n0 = blockIdx.x * 256, m0 = blockIdx.y * 128;

    int sec = 0;
    const __half* Abase = A0;
    if (mode == 0) { sec = blockIdx.x / 3; if (sec > 0) Abase = A1; }

    // loader mapping
    const int lrowA = tid >> 1;               // 0..127
    const int lcolA = (tid & 1) * 32;         // 0 / 32
    const int lrowB = tid;                    // 0..255
    const uint32_t sbase = smem_u32(smh);
    const uint32_t aDst = sbase + (uint32_t)(lrowA * LDH + lcolA) * 2u;
    const uint32_t bDst = sbase + (uint32_t)(A_TILE_H + lrowB * LDH) * 2u;
    const uint32_t aGbase = (uint32_t)(m0 + lrowA) * 768u + lcolA;
    const __half* bSrc = B + (size_t)(n0 + lrowB) * 768;

    float acc[4][8][4];
#pragma unroll
    for (int mt = 0; mt < 4; mt++)
#pragma unroll
        for (int nt = 0; nt < 8; nt++)
#pragma unroll
            for (int q = 0; q < 4; q++) acc[mt][nt][q] = 0.f;

    // prologue: chunks 0,1
#pragma unroll
    for (int s = 0; s < 2; s++) {
        uint32_t so = (uint32_t)(s * STG_H) * 2u;
        uint32_t k0 = s * 64;
#pragma unroll
        for (int c = 0; c < 4; c++) cp16(aDst + so + c * 16, Abase + ((aGbase + k0 + c * 8) & mask));
#pragma unroll
        for (int c = 0; c < 8; c++) cp16(bDst + so + c * 16, bSrc + k0 + c * 8);
        CP_COMMIT();
    }

    const int lrA = lane & 15, lcA = (lane >> 4) * 8;
    const int lrB = (lane & 7) + ((lane >> 4) << 3), lcB = ((lane >> 3) & 1) * 8;

    for (int i = 0; i < 12; i++) {
        CP_WAIT1();
        __syncthreads();

        const uint32_t smA = sbase + (uint32_t)((i & 1) * STG_H) * 2u;
        const uint32_t smB = smA + A_TILE_H * 2u;
#pragma unroll
        for (int ks = 0; ks < 4; ks++) {
            uint32_t a[4][4], b[4][4];
#pragma unroll
            for (int mt = 0; mt < 4; mt++)
                ldsm_x4(a[mt], smA + (uint32_t)((wm + mt * 16 + lrA) * LDH + ks * 16 + lcA) * 2u);
#pragma unroll
            for (int np = 0; np < 4; np++)
                ldsm_x4(b[np], smB + (uint32_t)((wn + np * 16 + lrB) * LDH + ks * 16 + lcB) * 2u);
#pragma unroll
            for (int mt = 0; mt < 4; mt++)
#pragma unroll
                for (int nt = 0; nt < 8; nt++)
                    mma_f16(acc[mt][nt], a[mt], &b[nt >> 1][(nt & 1) * 2]);
        }

        int j = i + 2;
        if (j < 12) {
            __syncthreads();   // everyone done reading slot (i&1) before refill
            uint32_t so = (uint32_t)((i & 1) * STG_H) * 2u;
            uint32_t k0 = j * 64;
#pragma unroll
            for (int c = 0; c < 4; c++) cp16(aDst + so + c * 16, Abase + ((aGbase + k0 + c * 8) & mask));
#pragma unroll
            for (int c = 0; c < 8; c++) cp16(bDst + so + c * 16, bSrc + k0 + c * 8);
            CP_COMMIT();
        }
    }

    // Epilogue
    __half* outp = hq;
    int colb = n0;
    if (mode == 0) {
        outp = (sec == 0) ? hq : (sec == 1 ? hk : hv);
        colb = n0 - sec * CDIM;
    }

#pragma unroll
    for (int mt = 0; mt < 4; mt++) {
        int r0 = m0 + wm + mt * 16 + g;
        int r1 = r0 + 8;
#pragma unroll
        for (int nt = 0; nt < 8; nt++) {
            int c = colb + wn + nt * 8 + 2 * t;
            if (mode == 0) {
                int head = c >> 6, d = c & 63;
                int w0 = r0 >> 6, nn0 = r0 & 63;
                int w1 = r1 >> 6, nn1 = r1 & 63;
                *(uint32_t*)(outp + (size_t)w0 * 49152 + head * 4096 + nn0 * 64 + d) =
                    packh2(acc[mt][nt][0], acc[mt][nt][1]);
                *(uint32_t*)(outp + (size_t)w1 * 49152 + head * 4096 + nn1 * 64 + d) =
                    packh2(acc[mt][nt][2], acc[mt][nt][3]);
            } else {
                float2 bv = *(const float2*)&bias[c];
                *(float2*)(outf + (size_t)r0 * CDIM + c) =
                    make_float2(acc[mt][nt][0] + bv.x, acc[mt][nt][1] + bv.y);
                *(float2*)(outf + (size_t)r1 * CDIM + c) =
                    make_float2(acc[mt][nt][2] + bv.x, acc[mt][nt][3] + bv.y);
            }
        }
    }
}

// ---------------------------------------------------------------------------
// K3: tensor-core windowed attention. One block per (window, head), 128 thr.
// S = q k^T * 0.125 (fp32 acc), softmax on fragments, O = P v via trans-ldsm.
// Output half into g_attnO (row-linear 65536x768).
// ---------------------------------------------------------------------------
#define ALD 72   // smem row stride in halfs

__global__ __launch_bounds__(128) void k_attn_h() {
    __shared__ __half sq[64 * ALD], sk[64 * ALD], sv[64 * ALD];
    const int wh = blockIdx.x;                 // win*12 + head
    const __half* qp = g_qh + (size_t)wh * 4096;
    const __half* kp = g_kh + (size_t)wh * 4096;
    const __half* vp = g_vh + (size_t)wh * 4096;
    const int tid = threadIdx.x, wid = tid >> 5, lane = tid & 31;
    const int g = lane >> 2, t = lane & 3;

    // load q,k,v (each 4096 halfs = 512 uint4)
#pragma unroll
    for (int u = 0; u < 4; u++) {
        int li = tid + u * 128;
        int row = li >> 3, c8 = li & 7;
        *(uint4*)&sq[row * ALD + c8 * 8] = ((const uint4*)qp)[li];
        *(uint4*)&sk[row * ALD + c8 * 8] = ((const uint4*)kp)[li];
        *(uint4*)&sv[row * ALD + c8 * 8] = ((const uint4*)vp)[li];
    }
    __syncthreads();

    const uint32_t sbq = smem_u32(sq), sbk = smem_u32(sk), sbv = smem_u32(sv);
    const int lrA = lane & 15, lcA = (lane >> 4) * 8;
    const int lrB = (lane & 7) + ((lane >> 4) << 3), lcB = ((lane >> 3) & 1) * 8;

    // ---- S = q k^T  (warp owns rows wid*16..+15; full 64 cols in 8 n-tiles) ----
    float sacc[8][4];
#pragma unroll
    for (int nt = 0; nt < 8; nt++)
#pragma unroll
        for (int q = 0; q < 4; q++) sacc[nt][q] = 0.f;

#pragma unroll
    for (int ks = 0; ks < 4; ks++) {
        uint32_t a[4], b[4][4];
        ldsm_x4(a, sbq + (uint32_t)((wid * 16 + lrA) * ALD + ks * 16 + lcA) * 2u);
#pragma unroll
        for (int np = 0; np < 4; np++)
            ldsm_x4(b[np], sbk + (uint32_t)((np * 16 + lrB) * ALD + ks * 16 + lcB) * 2u);
#pragma unroll
        for (int nt = 0; nt < 8; nt++)
            mma_f16(sacc[nt], a, &b[nt >> 1][(nt & 1) * 2]);
    }

    // ---- softmax on fragments (rows g and g+8 of this warp's 16-row block) ----
    float mx0 = -1e30f, mx1 = -1e30f;
#pragma unroll
    for (int nt = 0; nt < 8; nt++) {
#pragma unroll
        for (int q = 0; q < 4; q++) sacc[nt][q] *= 0.125f;
        mx0 = fmaxf(mx0, fmaxf(sacc[nt][0], sacc[nt][1]));
        mx1 = fmaxf(mx1, fmaxf(sacc[nt][2], sacc[nt][3]));
    }
    mx0 = fmaxf(mx0, __shfl_xor_sync(0xffffffffu, mx0, 1));
    mx0 = fmaxf(mx0, __shfl_xor_sync(0xffffffffu, mx0, 2));
    mx1 = fmaxf(mx1, __shfl_xor_sync(0xffffffffu, mx1, 1));
    mx1 = fmaxf(mx1, __shfl_xor_sync(0xffffffffu, mx1, 2));

    float sum0 = 0.f, sum1 = 0.f;
#pragma unroll
    for (int nt = 0; nt < 8; nt++) {
        sacc[nt][0] = __expf(sacc[nt][0] - mx0);
        sacc[nt][1] = __expf(sacc[nt][1] - mx0);
        sacc[nt][2] = __expf(sacc[nt][2] - mx1);
        sacc[nt][3] = __expf(sacc[nt][3] - mx1);
        sum0 += sacc[nt][0] + sacc[nt][1];
        sum1 += sacc[nt][2] + sacc[nt][3];
    }
    sum0 += __shfl_xor_sync(0xffffffffu, sum0, 1);
    sum0 += __shfl_xor_sync(0xffffffffu, sum0, 2);
    sum1 += __shfl_xor_sync(0xffffffffu, sum1, 1);
    sum1 += __shfl_xor_sync(0xffffffffu, sum1, 2);

    // ---- pack P into A fragments: pa[kt] covers k-dim (j) = kt*16 .. +15 ----
    uint32_t pa[4][4];
#pragma unroll
    for (int kt = 0; kt < 4; kt++) {
        pa[kt][0] = packh2(sacc[2 * kt][0],     sacc[2 * kt][1]);
        pa[kt][1] = packh2(sacc[2 * kt][2],     sacc[2 * kt][3]);
        pa[kt][2] = packh2(sacc[2 * kt + 1][0], sacc[2 * kt + 1][1]);
        pa[kt][3] = packh2(sacc[2 * kt + 1][2], sacc[2 * kt + 1][3]);
    }

    // ---- O = P v  (v[j][d] via ldmatrix.trans: B operand n=d, k=j) ----
    float oacc[8][4];
#pragma unroll
    for (int nt = 0; nt < 8; nt++)
#pragma unroll
        for (int q = 0; q < 4; q++) oacc[nt][q] = 0.f;

    const int lrV = (lane & 7) + (((lane >> 3) & 1) << 3);
    const int lcV = (lane >> 4) * 8;
#pragma unroll
    for (int kt = 0; kt < 4; kt++) {
        uint32_t b[4][4];
#pragma unroll
        for (int dp = 0; dp < 4; dp++)
            ldsm_x4_t(b[dp], sbv + (uint32_t)((kt * 16 + lrV) * ALD + dp * 16 + lcV) * 2u);
#pragma unroll
        for (int nt = 0; nt < 8; nt++)
            mma_f16(oacc[nt], pa[kt], &b[nt >> 1][(nt & 1) * 2]);
    }

    // ---- epilogue: normalize by row-sum, store half ----
    const float inv0 = 1.f / sum0, inv1 = 1.f / sum1;
    const int win = wh / 12, head = wh % 12;
    const int r0 = wid * 16 + g;
    __half* dst0 = g_attnO + (size_t)(win * 64 + r0) * CDIM + head * 64;
    __half* dst1 = g_attnO + (size_t)(win * 64 + r0 + 8) * CDIM + head * 64;
#pragma unroll
    for (int nt = 0; nt < 8; nt++) {
        int c = nt * 8 + 2 * t;
        *(uint32_t*)(dst0 + c) = packh2(oacc[nt][0] * inv0, oacc[nt][1] * inv0);
        *(uint32_t*)(dst1 + c) = packh2(oacc[nt][2] * inv1, oacc[nt][3] * inv1);
    }
}

// ---------------------------------------------------------------------------
// K5: LN2 + fc1 (row dot) + exact GELU + fc2 (outer product) + biases.
// ---------------------------------------------------------------------------
__global__ __launch_bounds__(256) void k_final(const float* __restrict__ g2,
                                               const float* __restrict__ b2,
                                               const float* __restrict__ fc1w,
                                               const float* __restrict__ fc1b,
                                               const float* __restrict__ fc2w,
                                               const float* __restrict__ fc2b,
                                               float* __restrict__ out) {
    __shared__ float sh[32];
    int r = blockIdx.x;
    const float* pr = g_po + (size_t)r * CDIM;
    int c0 = threadIdx.x, c1 = threadIdx.x + 256, c2 = threadIdx.x + 512;
    float v0 = pr[c0], v1 = pr[c1], v2 = pr[c2];

    float s  = v0 + v1 + v2;
    float sq = v0 * v0 + v1 * v1 + v2 * v2;
    blockReduce2(s, sq, sh);
    float mean = s * (1.f / 768.f);
    float var  = sq * (1.f / 768.f) - mean * mean;
    float rs   = rsqrtf(var + 1e-5f);

    float a0 = (v0 - mean) * rs * g2[c0] + b2[c0];
    float a1 = (v1 - mean) * rs * g2[c1] + b2[c1];
    float a2 = (v2 - mean) * rs * g2[c2] + b2[c2];

    float dotp = a0 * fc1w[c0] + a1 * fc1w[c1] + a2 * fc1w[c2];
    float zero = 0.f;
    blockReduce2(dotp, zero, sh);
    float t  = dotp + fc1b[0];
    float hd = 0.5f * t * (1.f + erff(t * 0.70710678118654752f));

    float* orow = out + (size_t)r * CDIM;
    orow[c0] = hd * fc2w[c0] + fc2b[c0];
    orow[c1] = hd * fc2w[c1] + fc2b[c1];
    orow[c2] = hd * fc2w[c2] + fc2b[c2];
}

// ---------------------------------------------------------------------------
// Host side
// ---------------------------------------------------------------------------
extern "C" void kernel_launch(void* const* d_in, const int* in_sizes, int n_in,
                              void* d_out, int out_size) {
    const float* x     = (const float*)d_in[0];
    const float* n1g   = (const float*)d_in[1];
    const float* n1b   = (const float*)d_in[2];
    const float* n2g   = (const float*)d_in[3];
    const float* n2b   = (const float*)d_in[4];
    const float* qkvw  = (const float*)d_in[5];
    const float* projw = (const float*)d_in[6];
    const float* projb = (const float*)d_in[7];
    const float* fc1w  = (const float*)d_in[8];
    const float* fc1b  = (const float*)d_in[9];
    const float* fc2w  = (const float*)d_in[10];
    const float* fc2b  = (const float*)d_in[11];

    void *pAh, *pAqh, *pQ, *pK, *pV, *pAO, *pPO, *pWq, *pWp;
    cudaGetSymbolAddress(&pAh, g_Ah);
    cudaGetSymbolAddress(&pAqh, g_Aqh);
    cudaGetSymbolAddress(&pQ, g_qh);
    cudaGetSymbolAddress(&pK, g_kh);
    cudaGetSymbolAddress(&pV, g_vh);
    cudaGetSymbolAddress(&pAO, g_attnO);
    cudaGetSymbolAddress(&pPO, g_po);
    cudaGetSymbolAddress(&pWq, g_Wqkvh);
    cudaGetSymbolAddress(&pWp, g_Wprojh);

    static bool attrSet = false;
    if (!attrSet) {
        cudaFuncSetAttribute(k_gemm_h, cudaFuncAttributeMaxDynamicSharedMemorySize, GSMEM_BYTES);
        attrSet = true;
    }

    k_toHalf<<<2304 * 768 / 4 / 256, 256>>>(qkvw, (__half*)pWq, 2304 * 768 / 4);
    k_toHalf<<<768 * 768 / 4 / 256, 256>>>(projw, (__half*)pWp, 768 * 768 / 4);

    k_ln1<<<NROWS, 256>>>(x, n1g, n1b);
    k_prep<<<QC / 4 / 256, 256>>>();

    dim3 gq(9, 512);
    k_gemm_h<<<gq, 256, GSMEM_BYTES>>>((const __half*)pAqh, (const __half*)pAh,
                                       (const __half*)pWq, MASKQ, 0, nullptr,
                                       (__half*)pQ, (__half*)pK, (__half*)pV, nullptr);

    k_attn_h<<<1024 * 12, 128>>>();

    dim3 gp(3, 512);
    k_gemm_h<<<gp, 256, GSMEM_BYTES>>>((const __half*)pAO, (const __half*)pAO,
                                       (const __half*)pWp, 0xFFFFFFFFu, 1, projb,
                                       nullptr, nullptr, nullptr, (float*)pPO);

    k_final<<<NROWS, 256>>>(n2g, n2b, fc1w, fc1b, fc2w, fc2b, (float*)d_out);
}